// round 4
// baseline (speedup 1.0000x reference)
#include <cuda_runtime.h>
#include <cuda_bf16.h>
#include <math.h>

// Problem constants
#define BB   16
#define SS   512
#define HH   768
#define II   3072
#define NHH  12
#define DHH  64
#define LL   6
#define M0   (BB*SS)       // 8192 tokens
#define NBA  (BB*NHH)      // 192 attention batches

// ---------------------------------------------------------------------------
// Scratch buffers (static __device__ globals: no runtime allocation)
// ---------------------------------------------------------------------------
__device__ float g_X[M0*HH];          // running hidden state
__device__ float g_Q[M0*HH];
__device__ float g_K[M0*HH];
__device__ float g_V[M0*HH];
__device__ float g_P[NBA*SS*SS];      // scores / probs (201 MB)
__device__ float g_C[M0*HH];          // attention context
__device__ float g_T[M0*HH];          // pre-layernorm tmp
__device__ float g_A[M0*HH];          // attn_out
__device__ float g_I[M0*II];          // FFN intermediate

// ---------------------------------------------------------------------------
// Generic tiled fp32 GEMM:
//   C[z][M,N] = alpha * A[z][M,K] @ op(B[z]) + bias + (residual | gelu)
// TRANSB=false: B is [K,N] row-major (ldb). TRANSB=true: B is [N,K] row-major.
// Batch offset: z -> (zb = z/zdiv, zh = z%zdiv); ptr += zb*s1 + zh*s2.
// EPI: 0 = bias only, 1 = bias + residual, 2 = bias + exact GELU
// ---------------------------------------------------------------------------
template<int BM,int BN,int BK,int TM,int TN,bool TRANSB,int EPI>
__global__ void __launch_bounds__((BM/TM)*(BN/TN))
gemm_k(const float* __restrict__ A, int lda,
       const float* __restrict__ B, int ldb,
       const float* __restrict__ bias,
       const float* __restrict__ R, int ldr,
       float* __restrict__ C, int ldc,
       int M, int N, int K, float alpha,
       long long sA1, long long sA2,
       long long sB1, long long sB2,
       long long sC1, long long sC2, int zdiv)
{
    constexpr int THREADS = (BM/TM)*(BN/TN);
    __shared__ __align__(16) float As[BK][BM];
    __shared__ __align__(16) float Bs[BK][BN];

    const int tid = threadIdx.x;
    const int zb = blockIdx.z / zdiv, zh = blockIdx.z % zdiv;
    A += zb*sA1 + zh*sA2;
    B += zb*sB1 + zh*sB2;
    C += zb*sC1 + zh*sC2;

    const int m0 = blockIdx.y * BM;
    const int n0 = blockIdx.x * BN;
    const int tx = tid % (BN/TN);
    const int ty = tid / (BN/TN);
    const int tm = ty * TM;
    const int tn = tx * TN;

    float acc[TM][TN] = {};

    for (int k0 = 0; k0 < K; k0 += BK) {
        // --- load A tile (row-major), store transposed As[k][m] ---
        #pragma unroll
        for (int it = 0; it < BM*BK/4/THREADS; ++it) {
            int id = tid + it*THREADS;
            int m  = id / (BK/4);
            int kv = id % (BK/4);
            const float4 v = *(const float4*)(A + (size_t)(m0+m)*lda + k0 + kv*4);
            As[kv*4+0][m] = v.x; As[kv*4+1][m] = v.y;
            As[kv*4+2][m] = v.z; As[kv*4+3][m] = v.w;
        }
        // --- load B tile into Bs[k][n] ---
        if (!TRANSB) {
            #pragma unroll
            for (int it = 0; it < BK*BN/4/THREADS; ++it) {
                int id = tid + it*THREADS;
                int kk = id / (BN/4);
                int nv = id % (BN/4);
                *(float4*)&Bs[kk][nv*4] =
                    *(const float4*)(B + (size_t)(k0+kk)*ldb + n0 + nv*4);
            }
        } else {
            #pragma unroll
            for (int it = 0; it < BN*BK/4/THREADS; ++it) {
                int id = tid + it*THREADS;
                int n  = id / (BK/4);
                int kv = id % (BK/4);
                const float4 v = *(const float4*)(B + (size_t)(n0+n)*ldb + k0 + kv*4);
                Bs[kv*4+0][n] = v.x; Bs[kv*4+1][n] = v.y;
                Bs[kv*4+2][n] = v.z; Bs[kv*4+3][n] = v.w;
            }
        }
        __syncthreads();

        #pragma unroll
        for (int kk = 0; kk < BK; ++kk) {
            float a[TM], b[TN];
            #pragma unroll
            for (int i = 0; i < TM; i += 4)
                *(float4*)&a[i] = *(const float4*)&As[kk][tm+i];
            #pragma unroll
            for (int j = 0; j < TN; j += 4)
                *(float4*)&b[j] = *(const float4*)&Bs[kk][tn+j];
            #pragma unroll
            for (int i = 0; i < TM; ++i)
                #pragma unroll
                for (int j = 0; j < TN; ++j)
                    acc[i][j] += a[i] * b[j];
        }
        __syncthreads();
    }

    // --- epilogue ---
    #pragma unroll
    for (int i = 0; i < TM; ++i) {
        const int gm = m0 + tm + i;
        #pragma unroll
        for (int j = 0; j < TN; ++j) {
            const int gn = n0 + tn + j;
            float v = acc[i][j] * alpha;
            if (bias) v += bias[gn];
            if (EPI == 1) v += R[(size_t)gm*ldr + gn];
            if (EPI == 2) v = 0.5f * v * (1.0f + erff(v * 0.70710678118654752f));
            C[(size_t)gm*ldc + gn] = v;
        }
    }
}

// ---------------------------------------------------------------------------
// Softmax over rows of length 512 (warp per row, fully in registers)
// ---------------------------------------------------------------------------
__global__ void softmax512(float* __restrict__ P, int rows)
{
    const int warp = (blockIdx.x * blockDim.x + threadIdx.x) >> 5;
    const int lane = threadIdx.x & 31;
    if (warp >= rows) return;
    float4* p = (float4*)(P + (size_t)warp * 512);

    float4 v[4];
    float mx = -3.4e38f;
    #pragma unroll
    for (int i = 0; i < 4; ++i) {
        v[i] = p[lane + i*32];
        mx = fmaxf(mx, fmaxf(fmaxf(v[i].x, v[i].y), fmaxf(v[i].z, v[i].w)));
    }
    #pragma unroll
    for (int o = 16; o; o >>= 1) mx = fmaxf(mx, __shfl_xor_sync(0xffffffffu, mx, o));

    float s = 0.0f;
    #pragma unroll
    for (int i = 0; i < 4; ++i) {
        v[i].x = expf(v[i].x - mx); v[i].y = expf(v[i].y - mx);
        v[i].z = expf(v[i].z - mx); v[i].w = expf(v[i].w - mx);
        s += v[i].x + v[i].y + v[i].z + v[i].w;
    }
    #pragma unroll
    for (int o = 16; o; o >>= 1) s += __shfl_xor_sync(0xffffffffu, s, o);
    const float inv = 1.0f / s;
    #pragma unroll
    for (int i = 0; i < 4; ++i) {
        v[i].x *= inv; v[i].y *= inv; v[i].z *= inv; v[i].w *= inv;
        p[lane + i*32] = v[i];
    }
}

// ---------------------------------------------------------------------------
// LayerNorm over rows of length 768 (warp per row)
// ---------------------------------------------------------------------------
__global__ void layernorm768(const float* __restrict__ X,
                             const float* __restrict__ g,
                             const float* __restrict__ b,
                             float* __restrict__ Y, int rows)
{
    const int warp = (blockIdx.x * blockDim.x + threadIdx.x) >> 5;
    const int lane = threadIdx.x & 31;
    if (warp >= rows) return;
    const float4* x = (const float4*)(X + (size_t)warp * 768);

    float4 v[6];
    float s = 0.0f;
    #pragma unroll
    for (int i = 0; i < 6; ++i) {
        v[i] = x[lane + i*32];
        s += v[i].x + v[i].y + v[i].z + v[i].w;
    }
    #pragma unroll
    for (int o = 16; o; o >>= 1) s += __shfl_xor_sync(0xffffffffu, s, o);
    const float mean = s * (1.0f / 768.0f);

    float var = 0.0f;
    #pragma unroll
    for (int i = 0; i < 6; ++i) {
        float dx = v[i].x - mean, dy = v[i].y - mean, dz = v[i].z - mean, dw = v[i].w - mean;
        var += dx*dx + dy*dy + dz*dz + dw*dw;
    }
    #pragma unroll
    for (int o = 16; o; o >>= 1) var += __shfl_xor_sync(0xffffffffu, var, o);
    const float rs = rsqrtf(var * (1.0f / 768.0f) + 1e-12f);

    float4* y = (float4*)(Y + (size_t)warp * 768);
    const float4* gg = (const float4*)g;
    const float4* bb = (const float4*)b;
    #pragma unroll
    for (int i = 0; i < 6; ++i) {
        const int c = lane + i*32;
        const float4 gv = gg[c], bv = bb[c];
        float4 o4;
        o4.x = (v[i].x - mean) * rs * gv.x + bv.x;
        o4.y = (v[i].y - mean) * rs * gv.y + bv.y;
        o4.z = (v[i].z - mean) * rs * gv.z + bv.z;
        o4.w = (v[i].w - mean) * rs * gv.w + bv.w;
        y[c] = o4;
    }
}

// ---------------------------------------------------------------------------
// Launch
// ---------------------------------------------------------------------------
extern "C" void kernel_launch(void* const* d_in, const int* in_sizes, int n_in,
                              void* d_out, int out_size)
{
    (void)in_sizes; (void)n_in; (void)out_size;
    const float* hs  = (const float*)d_in[0];
    const float* Wq  = (const float*)d_in[1];  const float* bq  = (const float*)d_in[2];
    const float* Wk  = (const float*)d_in[3];  const float* bk  = (const float*)d_in[4];
    const float* Wv  = (const float*)d_in[5];  const float* bv  = (const float*)d_in[6];
    const float* Wo  = (const float*)d_in[7];  const float* bo  = (const float*)d_in[8];
    const float* g1  = (const float*)d_in[9];  const float* b1  = (const float*)d_in[10];
    const float* Wi  = (const float*)d_in[11]; const float* bi  = (const float*)d_in[12];
    const float* Wo2 = (const float*)d_in[13]; const float* bo2 = (const float*)d_in[14];
    const float* g2  = (const float*)d_in[15]; const float* b2  = (const float*)d_in[16];

    float *X, *Q, *Kb, *V, *P, *Cx, *T, *Aa, *Ib;
    cudaGetSymbolAddress((void**)&X,  g_X);
    cudaGetSymbolAddress((void**)&Q,  g_Q);
    cudaGetSymbolAddress((void**)&Kb, g_K);
    cudaGetSymbolAddress((void**)&V,  g_V);
    cudaGetSymbolAddress((void**)&P,  g_P);
    cudaGetSymbolAddress((void**)&Cx, g_C);
    cudaGetSymbolAddress((void**)&T,  g_T);
    cudaGetSymbolAddress((void**)&Aa, g_A);
    cudaGetSymbolAddress((void**)&Ib, g_I);

    cudaMemcpyAsync(X, hs, sizeof(float)*(size_t)M0*HH, cudaMemcpyDeviceToDevice, 0);

    const long long sQ1 = (long long)SS*HH;   // per-b stride in Q/K/V/ctx views
    const long long sQ2 = DHH;                // per-head stride
    const long long sP1 = (long long)NHH*SS*SS;
    const long long sP2 = (long long)SS*SS;

    for (int l = 0; l < LL; ++l) {
        const float* wq  = Wq  + (size_t)l*HH*HH; const float* bql  = bq  + (size_t)l*HH;
        const float* wk  = Wk  + (size_t)l*HH*HH; const float* bkl  = bk  + (size_t)l*HH;
        const float* wv  = Wv  + (size_t)l*HH*HH; const float* bvl  = bv  + (size_t)l*HH;
        const float* wo  = Wo  + (size_t)l*HH*HH; const float* bol  = bo  + (size_t)l*HH;
        const float* wi  = Wi  + (size_t)l*HH*II; const float* bil  = bi  + (size_t)l*II;
        const float* wo2 = Wo2 + (size_t)l*II*HH; const float* bo2l = bo2 + (size_t)l*HH;

        // Q, K, V projections: [8192,768] = X @ W + b
        dim3 gp(HH/128, M0/128, 1);
        gemm_k<128,128,16,8,8,false,0><<<gp,256>>>(X,HH, wq,HH, bql, nullptr,0, Q ,HH,
            M0,HH,HH, 1.0f, 0,0,0,0,0,0, 1);
        gemm_k<128,128,16,8,8,false,0><<<gp,256>>>(X,HH, wk,HH, bkl, nullptr,0, Kb,HH,
            M0,HH,HH, 1.0f, 0,0,0,0,0,0, 1);
        gemm_k<128,128,16,8,8,false,0><<<gp,256>>>(X,HH, wv,HH, bvl, nullptr,0, V ,HH,
            M0,HH,HH, 1.0f, 0,0,0,0,0,0, 1);

        // scores[b,h] = Q_bh @ K_bh^T / 8   (M=N=512, K=64, 192 batches)
        dim3 gs(SS/128, SS/128, NBA);
        gemm_k<128,128,16,8,8,true,0><<<gs,256>>>(Q,HH, Kb,HH, nullptr, nullptr,0, P,SS,
            SS,SS,DHH, 0.125f, sQ1,sQ2, sQ1,sQ2, sP1,sP2, NHH);

        // softmax over last dim
        softmax512<<<(NBA*SS)/8, 256>>>(P, NBA*SS);

        // ctx[b,h] = probs @ V_bh   (M=512, N=64, K=512)
        dim3 gc(1, SS/64, NBA);
        gemm_k<64,64,16,4,4,false,0><<<gc,256>>>(P,SS, V,HH, nullptr, nullptr,0, Cx,HH,
            SS,DHH,SS, 1.0f, sP1,sP2, sQ1,sQ2, sQ1,sQ2, NHH);

        // O projection + residual: T = ctx @ Wo + bo + X
        gemm_k<128,128,16,8,8,false,1><<<gp,256>>>(Cx,HH, wo,HH, bol, X,HH, T,HH,
            M0,HH,HH, 1.0f, 0,0,0,0,0,0, 1);
        // attn_out = LN(T)
        layernorm768<<<M0/8,256>>>(T, g1 + (size_t)l*HH, b1 + (size_t)l*HH, Aa, M0);

        // FFN1: I = gelu(attn_out @ Wi + bi)   (N=3072)
        dim3 gf1(II/128, M0/128, 1);
        gemm_k<128,128,16,8,8,false,2><<<gf1,256>>>(Aa,HH, wi,II, bil, nullptr,0, Ib,II,
            M0,II,HH, 1.0f, 0,0,0,0,0,0, 1);

        // FFN2 + residual: T = I @ Wo2 + bo2 + attn_out   (K=3072)
        gemm_k<128,128,16,8,8,false,1><<<gp,256>>>(Ib,II, wo2,HH, bo2l, Aa,HH, T,HH,
            M0,HH,II, 1.0f, 0,0,0,0,0,0, 1);

        // out = LN(T) -> X (or d_out on last layer)
        float* outX = (l == LL-1) ? (float*)d_out : X;
        layernorm768<<<M0/8,256>>>(T, g2 + (size_t)l*HH, b2 + (size_t)l*HH, outX, M0);
    }
}

// round 5
// speedup vs baseline: 1.0035x; 1.0035x over previous
#include <cuda_runtime.h>
#include <cuda_bf16.h>
#include <math.h>

// Problem constants
#define BB   16
#define SS   512
#define HH   768
#define II   3072
#define NHH  12
#define DHH  64
#define LL   6
#define M0   (BB*SS)       // 8192 tokens
#define NBA  (BB*NHH)      // 192 attention batches

// ---------------------------------------------------------------------------
// Scratch buffers (static __device__ globals: no runtime allocation)
// ---------------------------------------------------------------------------
__device__ float g_X[M0*HH];          // running hidden state
__device__ float g_Q[M0*HH];
__device__ float g_K[M0*HH];
__device__ float g_V[M0*HH];
__device__ float g_P[NBA*SS*SS];      // scores / probs (201 MB)
__device__ float g_C[M0*HH];          // attention context
__device__ float g_T[M0*HH];          // pre-layernorm tmp
__device__ float g_A[M0*HH];          // attn_out
__device__ float g_I[M0*II];          // FFN intermediate

// ---------------------------------------------------------------------------
// Generic tiled fp32 GEMM:
//   C[z][M,N] = alpha * A[z][M,K] @ op(B[z]) + bias + (residual | gelu)
// TRANSB=false: B is [K,N] row-major (ldb). TRANSB=true: B is [N,K] row-major.
// Batch offset: z -> (zb = z/zdiv, zh = z%zdiv); ptr += zb*s1 + zh*s2.
// EPI: 0 = bias only, 1 = bias + residual, 2 = bias + exact GELU
// ---------------------------------------------------------------------------
template<int BM,int BN,int BK,int TM,int TN,bool TRANSB,int EPI>
__global__ void __launch_bounds__((BM/TM)*(BN/TN))
gemm_k(const float* __restrict__ A, int lda,
       const float* __restrict__ B, int ldb,
       const float* __restrict__ bias,
       const float* __restrict__ R, int ldr,
       float* __restrict__ C, int ldc,
       int M, int N, int K, float alpha,
       long long sA1, long long sA2,
       long long sB1, long long sB2,
       long long sC1, long long sC2, int zdiv)
{
    constexpr int THREADS = (BM/TM)*(BN/TN);
    __shared__ __align__(16) float As[BK][BM];
    __shared__ __align__(16) float Bs[BK][BN];

    const int tid = threadIdx.x;
    const int zb = blockIdx.z / zdiv, zh = blockIdx.z % zdiv;
    A += zb*sA1 + zh*sA2;
    B += zb*sB1 + zh*sB2;
    C += zb*sC1 + zh*sC2;

    const int m0 = blockIdx.y * BM;
    const int n0 = blockIdx.x * BN;
    const int tx = tid % (BN/TN);
    const int ty = tid / (BN/TN);
    const int tm = ty * TM;
    const int tn = tx * TN;

    float acc[TM][TN] = {};

    for (int k0 = 0; k0 < K; k0 += BK) {
        // --- load A tile (row-major), store transposed As[k][m] ---
        #pragma unroll
        for (int it = 0; it < BM*BK/4/THREADS; ++it) {
            int id = tid + it*THREADS;
            int m  = id / (BK/4);
            int kv = id % (BK/4);
            const float4 v = *(const float4*)(A + (size_t)(m0+m)*lda + k0 + kv*4);
            As[kv*4+0][m] = v.x; As[kv*4+1][m] = v.y;
            As[kv*4+2][m] = v.z; As[kv*4+3][m] = v.w;
        }
        // --- load B tile into Bs[k][n] ---
        if (!TRANSB) {
            #pragma unroll
            for (int it = 0; it < BK*BN/4/THREADS; ++it) {
                int id = tid + it*THREADS;
                int kk = id / (BN/4);
                int nv = id % (BN/4);
                *(float4*)&Bs[kk][nv*4] =
                    *(const float4*)(B + (size_t)(k0+kk)*ldb + n0 + nv*4);
            }
        } else {
            #pragma unroll
            for (int it = 0; it < BN*BK/4/THREADS; ++it) {
                int id = tid + it*THREADS;
                int n  = id / (BK/4);
                int kv = id % (BK/4);
                const float4 v = *(const float4*)(B + (size_t)(n0+n)*ldb + k0 + kv*4);
                Bs[kv*4+0][n] = v.x; Bs[kv*4+1][n] = v.y;
                Bs[kv*4+2][n] = v.z; Bs[kv*4+3][n] = v.w;
            }
        }
        __syncthreads();

        #pragma unroll
        for (int kk = 0; kk < BK; ++kk) {
            float a[TM], b[TN];
            #pragma unroll
            for (int i = 0; i < TM; i += 4)
                *(float4*)&a[i] = *(const float4*)&As[kk][tm+i];
            #pragma unroll
            for (int j = 0; j < TN; j += 4)
                *(float4*)&b[j] = *(const float4*)&Bs[kk][tn+j];
            #pragma unroll
            for (int i = 0; i < TM; ++i)
                #pragma unroll
                for (int j = 0; j < TN; ++j)
                    acc[i][j] += a[i] * b[j];
        }
        __syncthreads();
    }

    // --- epilogue ---
    #pragma unroll
    for (int i = 0; i < TM; ++i) {
        const int gm = m0 + tm + i;
        #pragma unroll
        for (int j = 0; j < TN; ++j) {
            const int gn = n0 + tn + j;
            float v = acc[i][j] * alpha;
            if (bias) v += bias[gn];
            if (EPI == 1) v += R[(size_t)gm*ldr + gn];
            if (EPI == 2) v = 0.5f * v * (1.0f + erff(v * 0.70710678118654752f));
            C[(size_t)gm*ldc + gn] = v;
        }
    }
}

// ---------------------------------------------------------------------------
// Softmax over rows of length 512 (warp per row, fully in registers)
// ---------------------------------------------------------------------------
__global__ void softmax512(float* __restrict__ P, int rows)
{
    const int warp = (blockIdx.x * blockDim.x + threadIdx.x) >> 5;
    const int lane = threadIdx.x & 31;
    if (warp >= rows) return;
    float4* p = (float4*)(P + (size_t)warp * 512);

    float4 v[4];
    float mx = -3.4e38f;
    #pragma unroll
    for (int i = 0; i < 4; ++i) {
        v[i] = p[lane + i*32];
        mx = fmaxf(mx, fmaxf(fmaxf(v[i].x, v[i].y), fmaxf(v[i].z, v[i].w)));
    }
    #pragma unroll
    for (int o = 16; o; o >>= 1) mx = fmaxf(mx, __shfl_xor_sync(0xffffffffu, mx, o));

    float s = 0.0f;
    #pragma unroll
    for (int i = 0; i < 4; ++i) {
        v[i].x = expf(v[i].x - mx); v[i].y = expf(v[i].y - mx);
        v[i].z = expf(v[i].z - mx); v[i].w = expf(v[i].w - mx);
        s += v[i].x + v[i].y + v[i].z + v[i].w;
    }
    #pragma unroll
    for (int o = 16; o; o >>= 1) s += __shfl_xor_sync(0xffffffffu, s, o);
    const float inv = 1.0f / s;
    #pragma unroll
    for (int i = 0; i < 4; ++i) {
        v[i].x *= inv; v[i].y *= inv; v[i].z *= inv; v[i].w *= inv;
        p[lane + i*32] = v[i];
    }
}

// ---------------------------------------------------------------------------
// LayerNorm over rows of length 768 (warp per row)
// ---------------------------------------------------------------------------
__global__ void layernorm768(const float* __restrict__ X,
                             const float* __restrict__ g,
                             const float* __restrict__ b,
                             float* __restrict__ Y, int rows)
{
    const int warp = (blockIdx.x * blockDim.x + threadIdx.x) >> 5;
    const int lane = threadIdx.x & 31;
    if (warp >= rows) return;
    const float4* x = (const float4*)(X + (size_t)warp * 768);

    float4 v[6];
    float s = 0.0f;
    #pragma unroll
    for (int i = 0; i < 6; ++i) {
        v[i] = x[lane + i*32];
        s += v[i].x + v[i].y + v[i].z + v[i].w;
    }
    #pragma unroll
    for (int o = 16; o; o >>= 1) s += __shfl_xor_sync(0xffffffffu, s, o);
    const float mean = s * (1.0f / 768.0f);

    float var = 0.0f;
    #pragma unroll
    for (int i = 0; i < 6; ++i) {
        float dx = v[i].x - mean, dy = v[i].y - mean, dz = v[i].z - mean, dw = v[i].w - mean;
        var += dx*dx + dy*dy + dz*dz + dw*dw;
    }
    #pragma unroll
    for (int o = 16; o; o >>= 1) var += __shfl_xor_sync(0xffffffffu, var, o);
    const float rs = rsqrtf(var * (1.0f / 768.0f) + 1e-12f);

    float4* y = (float4*)(Y + (size_t)warp * 768);
    const float4* gg = (const float4*)g;
    const float4* bb = (const float4*)b;
    #pragma unroll
    for (int i = 0; i < 6; ++i) {
        const int c = lane + i*32;
        const float4 gv = gg[c], bv = bb[c];
        float4 o4;
        o4.x = (v[i].x - mean) * rs * gv.x + bv.x;
        o4.y = (v[i].y - mean) * rs * gv.y + bv.y;
        o4.z = (v[i].z - mean) * rs * gv.z + bv.z;
        o4.w = (v[i].w - mean) * rs * gv.w + bv.w;
        y[c] = o4;
    }
}

// ---------------------------------------------------------------------------
// Launch
// ---------------------------------------------------------------------------
extern "C" void kernel_launch(void* const* d_in, const int* in_sizes, int n_in,
                              void* d_out, int out_size)
{
    (void)in_sizes; (void)n_in; (void)out_size;
    const float* hs  = (const float*)d_in[0];
    const float* Wq  = (const float*)d_in[1];  const float* bq  = (const float*)d_in[2];
    const float* Wk  = (const float*)d_in[3];  const float* bk  = (const float*)d_in[4];
    const float* Wv  = (const float*)d_in[5];  const float* bv  = (const float*)d_in[6];
    const float* Wo  = (const float*)d_in[7];  const float* bo  = (const float*)d_in[8];
    const float* g1  = (const float*)d_in[9];  const float* b1  = (const float*)d_in[10];
    const float* Wi  = (const float*)d_in[11]; const float* bi  = (const float*)d_in[12];
    const float* Wo2 = (const float*)d_in[13]; const float* bo2 = (const float*)d_in[14];
    const float* g2  = (const float*)d_in[15]; const float* b2  = (const float*)d_in[16];

    float *X, *Q, *Kb, *V, *P, *Cx, *T, *Aa, *Ib;
    cudaGetSymbolAddress((void**)&X,  g_X);
    cudaGetSymbolAddress((void**)&Q,  g_Q);
    cudaGetSymbolAddress((void**)&Kb, g_K);
    cudaGetSymbolAddress((void**)&V,  g_V);
    cudaGetSymbolAddress((void**)&P,  g_P);
    cudaGetSymbolAddress((void**)&Cx, g_C);
    cudaGetSymbolAddress((void**)&T,  g_T);
    cudaGetSymbolAddress((void**)&Aa, g_A);
    cudaGetSymbolAddress((void**)&Ib, g_I);

    cudaMemcpyAsync(X, hs, sizeof(float)*(size_t)M0*HH, cudaMemcpyDeviceToDevice, 0);

    const long long sQ1 = (long long)SS*HH;   // per-b stride in Q/K/V/ctx views
    const long long sQ2 = DHH;                // per-head stride
    const long long sP1 = (long long)NHH*SS*SS;
    const long long sP2 = (long long)SS*SS;

    for (int l = 0; l < LL; ++l) {
        const float* wq  = Wq  + (size_t)l*HH*HH; const float* bql  = bq  + (size_t)l*HH;
        const float* wk  = Wk  + (size_t)l*HH*HH; const float* bkl  = bk  + (size_t)l*HH;
        const float* wv  = Wv  + (size_t)l*HH*HH; const float* bvl  = bv  + (size_t)l*HH;
        const float* wo  = Wo  + (size_t)l*HH*HH; const float* bol  = bo  + (size_t)l*HH;
        const float* wi  = Wi  + (size_t)l*HH*II; const float* bil  = bi  + (size_t)l*II;
        const float* wo2 = Wo2 + (size_t)l*II*HH; const float* bo2l = bo2 + (size_t)l*HH;

        // Q, K, V projections: [8192,768] = X @ W + b
        dim3 gp(HH/128, M0/128, 1);
        gemm_k<128,128,16,8,8,false,0><<<gp,256>>>(X,HH, wq,HH, bql, nullptr,0, Q ,HH,
            M0,HH,HH, 1.0f, 0,0,0,0,0,0, 1);
        gemm_k<128,128,16,8,8,false,0><<<gp,256>>>(X,HH, wk,HH, bkl, nullptr,0, Kb,HH,
            M0,HH,HH, 1.0f, 0,0,0,0,0,0, 1);
        gemm_k<128,128,16,8,8,false,0><<<gp,256>>>(X,HH, wv,HH, bvl, nullptr,0, V ,HH,
            M0,HH,HH, 1.0f, 0,0,0,0,0,0, 1);

        // scores[b,h] = Q_bh @ K_bh^T / 8   (M=N=512, K=64, 192 batches)
        dim3 gs(SS/128, SS/128, NBA);
        gemm_k<128,128,16,8,8,true,0><<<gs,256>>>(Q,HH, Kb,HH, nullptr, nullptr,0, P,SS,
            SS,SS,DHH, 0.125f, sQ1,sQ2, sQ1,sQ2, sP1,sP2, NHH);

        // softmax over last dim
        softmax512<<<(NBA*SS)/8, 256>>>(P, NBA*SS);

        // ctx[b,h] = probs @ V_bh   (M=512, N=64, K=512)
        dim3 gc(1, SS/64, NBA);
        gemm_k<64,64,16,4,4,false,0><<<gc,256>>>(P,SS, V,HH, nullptr, nullptr,0, Cx,HH,
            SS,DHH,SS, 1.0f, sP1,sP2, sQ1,sQ2, sQ1,sQ2, NHH);

        // O projection + residual: T = ctx @ Wo + bo + X
        gemm_k<128,128,16,8,8,false,1><<<gp,256>>>(Cx,HH, wo,HH, bol, X,HH, T,HH,
            M0,HH,HH, 1.0f, 0,0,0,0,0,0, 1);
        // attn_out = LN(T)
        layernorm768<<<M0/8,256>>>(T, g1 + (size_t)l*HH, b1 + (size_t)l*HH, Aa, M0);

        // FFN1: I = gelu(attn_out @ Wi + bi)   (N=3072)
        dim3 gf1(II/128, M0/128, 1);
        gemm_k<128,128,16,8,8,false,2><<<gf1,256>>>(Aa,HH, wi,II, bil, nullptr,0, Ib,II,
            M0,II,HH, 1.0f, 0,0,0,0,0,0, 1);

        // FFN2 + residual: T = I @ Wo2 + bo2 + attn_out   (K=3072)
        gemm_k<128,128,16,8,8,false,1><<<gp,256>>>(Ib,II, wo2,HH, bo2l, Aa,HH, T,HH,
            M0,HH,II, 1.0f, 0,0,0,0,0,0, 1);

        // out = LN(T) -> X (or d_out on last layer)
        float* outX = (l == LL-1) ? (float*)d_out : X;
        layernorm768<<<M0/8,256>>>(T, g2 + (size_t)l*HH, b2 + (size_t)l*HH, outX, M0);
    }
}

// round 6
// speedup vs baseline: 2.5118x; 2.5030x over previous
#include <cuda_runtime.h>
#include <cuda_bf16.h>
#include <math.h>
#include <stdint.h>

// Problem constants
#define BB   16
#define SS   512
#define HH   768
#define II   3072
#define NHH  12
#define DHH  64
#define LL   6
#define M0   (BB*SS)       // 8192 tokens
#define NBA  (BB*NHH)      // 192 attention batches

// ---------------------------------------------------------------------------
// Scratch buffers
// ---------------------------------------------------------------------------
__device__ float g_X[M0*HH];
__device__ float g_Q[M0*HH];
__device__ float g_K[M0*HH];
__device__ float g_V[M0*HH];
__device__ float g_P[NBA*SS*SS];      // scores / probs
__device__ float g_C[M0*HH];
__device__ float g_T[M0*HH];
__device__ float g_A[M0*HH];
__device__ float g_I[M0*II];

// ---------------------------------------------------------------------------
// PTX helpers
// ---------------------------------------------------------------------------
__device__ __forceinline__ uint32_t smem_u32(const void* p) {
    return (uint32_t)__cvta_generic_to_shared(p);
}
__device__ __forceinline__ void ldsm_x4(uint32_t* r, uint32_t a) {
    asm volatile("ldmatrix.sync.aligned.m8n8.x4.shared.b16 {%0,%1,%2,%3}, [%4];"
        : "=r"(r[0]), "=r"(r[1]), "=r"(r[2]), "=r"(r[3]) : "r"(a));
}
__device__ __forceinline__ void ldsm_x4t(uint32_t* r, uint32_t a) {
    asm volatile("ldmatrix.sync.aligned.m8n8.x4.trans.shared.b16 {%0,%1,%2,%3}, [%4];"
        : "=r"(r[0]), "=r"(r[1]), "=r"(r[2]), "=r"(r[3]) : "r"(a));
}
__device__ __forceinline__ void mma16816(float* c, const uint32_t* a, const uint32_t* b) {
    asm volatile(
        "mma.sync.aligned.m16n8k16.row.col.f32.bf16.bf16.f32 "
        "{%0,%1,%2,%3}, {%4,%5,%6,%7}, {%8,%9}, {%0,%1,%2,%3};"
        : "+f"(c[0]), "+f"(c[1]), "+f"(c[2]), "+f"(c[3])
        : "r"(a[0]), "r"(a[1]), "r"(a[2]), "r"(a[3]), "r"(b[0]), "r"(b[1]));
}

// fp32 -> (bf16 hi, bf16 lo) exact-residual split
__device__ __forceinline__ void split1(float x, unsigned short& hi, unsigned short& lo) {
    __nv_bfloat16 h = __float2bfloat16(x);
    hi = *reinterpret_cast<unsigned short*>(&h);
    float r = x - __bfloat162float(h);
    __nv_bfloat16 l = __float2bfloat16(r);
    lo = *reinterpret_cast<unsigned short*>(&l);
}
__device__ __forceinline__ void split4(float4 v, ushort4& hi, ushort4& lo) {
    split1(v.x, hi.x, lo.x);
    split1(v.y, hi.y, lo.y);
    split1(v.z, hi.z, lo.z);
    split1(v.w, hi.w, lo.w);
}

// ---------------------------------------------------------------------------
// bf16x3 split-precision tensor-core GEMM
//   C[z][M,N] = alpha * A[z][M,K] @ op(B[z]) + bias + (residual | gelu)
// TRANSB=false: B is [K,N] row-major (ldb). TRANSB=true: B is [N,K] row-major.
// Batch: z -> (zb = z/zdiv, zh = z%zdiv); ptr += zb*s1 + zh*s2.
// EPI: 0 = (bias), 1 = bias + residual, 2 = bias + exact GELU
// ---------------------------------------------------------------------------
template<int BM, int BN, int BK, int WM, int WN, bool TRANSB, int EPI>
__global__ void __launch_bounds__(WM*WN*32)
gemm_mma(const float* __restrict__ A, int lda,
         const float* __restrict__ B, int ldb,
         const float* __restrict__ bias,
         const float* __restrict__ R, int ldr,
         float* __restrict__ C, int ldc,
         int M, int N, int K, float alpha,
         long long sA1, long long sA2,
         long long sB1, long long sB2,
         long long sC1, long long sC2, int zdiv)
{
    constexpr int THREADS = WM*WN*32;
    constexpr int WTM = BM/WM, WTN = BN/WN;   // warp tile
    constexpr int MT = WTM/16, NT = WTN/8;    // mma tiles per warp
    constexpr int PAD = 8;
    constexpr int AIT = BM*BK/4/THREADS;      // float4 loads per thread (A)
    constexpr int BIT = BK*BN/4/THREADS;      // float4 loads per thread (B)

    __shared__ __align__(16) unsigned short Ah[BM][BK+PAD];
    __shared__ __align__(16) unsigned short Al[BM][BK+PAD];
    __shared__ __align__(16) unsigned short Bh[BK][BN+PAD];
    __shared__ __align__(16) unsigned short Bl[BK][BN+PAD];

    const int tid  = threadIdx.x;
    const int lane = tid & 31;
    const int wid  = tid >> 5;
    const int wm   = wid / WN;
    const int wn   = wid % WN;

    const int zb = blockIdx.z / zdiv, zh = blockIdx.z % zdiv;
    A += zb*sA1 + zh*sA2;
    B += zb*sB1 + zh*sB2;
    C += zb*sC1 + zh*sC2;

    const int m0 = blockIdx.y * BM;
    const int n0 = blockIdx.x * BN;

    float acc[MT][NT][4] = {};

    float4 ra[AIT], rb[BIT];

    auto loadA = [&](int k0) {
        #pragma unroll
        for (int it = 0; it < AIT; ++it) {
            int id = tid + it*THREADS;
            int m  = id / (BK/4), kv = id % (BK/4);
            ra[it] = *(const float4*)(A + (size_t)(m0+m)*lda + k0 + kv*4);
        }
    };
    auto loadB = [&](int k0) {
        #pragma unroll
        for (int it = 0; it < BIT; ++it) {
            int id = tid + it*THREADS;
            if constexpr (!TRANSB) {
                int kk = id / (BN/4), nv = id % (BN/4);
                rb[it] = *(const float4*)(B + (size_t)(k0+kk)*ldb + n0 + nv*4);
            } else {
                int n = id / (BK/4), kv = id % (BK/4);
                rb[it] = *(const float4*)(B + (size_t)(n0+n)*ldb + k0 + kv*4);
            }
        }
    };
    auto storeAB = [&]() {
        #pragma unroll
        for (int it = 0; it < AIT; ++it) {
            int id = tid + it*THREADS;
            int m  = id / (BK/4), kv = id % (BK/4);
            ushort4 hi, lo; split4(ra[it], hi, lo);
            *(ushort4*)&Ah[m][kv*4] = hi;
            *(ushort4*)&Al[m][kv*4] = lo;
        }
        #pragma unroll
        for (int it = 0; it < BIT; ++it) {
            int id = tid + it*THREADS;
            ushort4 hi, lo; split4(rb[it], hi, lo);
            if constexpr (!TRANSB) {
                int kk = id / (BN/4), nv = id % (BN/4);
                *(ushort4*)&Bh[kk][nv*4] = hi;
                *(ushort4*)&Bl[kk][nv*4] = lo;
            } else {
                int n = id / (BK/4), kv = id % (BK/4);
                Bh[kv*4+0][n] = hi.x; Bh[kv*4+1][n] = hi.y;
                Bh[kv*4+2][n] = hi.z; Bh[kv*4+3][n] = hi.w;
                Bl[kv*4+0][n] = lo.x; Bl[kv*4+1][n] = lo.y;
                Bl[kv*4+2][n] = lo.z; Bl[kv*4+3][n] = lo.w;
            }
        }
    };

    const int nk = K / BK;
    loadA(0); loadB(0);

    for (int kt = 0; kt < nk; ++kt) {
        storeAB();
        __syncthreads();
        if (kt + 1 < nk) { loadA((kt+1)*BK); loadB((kt+1)*BK); }  // prefetch overlaps MMA

        #pragma unroll
        for (int ks = 0; ks < BK/16; ++ks) {
            uint32_t ah[MT][4], al[MT][4];
            #pragma unroll
            for (int mt = 0; mt < MT; ++mt) {
                int r = wm*WTM + mt*16 + (lane & 15);
                int c = ks*16 + ((lane >> 4) << 3);
                ldsm_x4(ah[mt], smem_u32(&Ah[r][c]));
                ldsm_x4(al[mt], smem_u32(&Al[r][c]));
            }
            #pragma unroll
            for (int np = 0; np < NT/2; ++np) {
                uint32_t bh[4], bl[4];
                int rr = ks*16 + (lane & 15);
                int cc = wn*WTN + np*16 + ((lane >> 4) << 3);
                ldsm_x4t(bh, smem_u32(&Bh[rr][cc]));
                ldsm_x4t(bl, smem_u32(&Bl[rr][cc]));
                #pragma unroll
                for (int s = 0; s < 2; ++s) {
                    const int nt = np*2 + s;
                    #pragma unroll
                    for (int mt = 0; mt < MT; ++mt) {
                        mma16816(acc[mt][nt], ah[mt], bh + s*2);  // hi*hi
                        mma16816(acc[mt][nt], al[mt], bh + s*2);  // lo*hi
                        mma16816(acc[mt][nt], ah[mt], bl + s*2);  // hi*lo
                    }
                }
            }
        }
        __syncthreads();
    }

    // --- epilogue ---
    #pragma unroll
    for (int mt = 0; mt < MT; ++mt) {
        #pragma unroll
        for (int nt = 0; nt < NT; ++nt) {
            const int row = m0 + wm*WTM + mt*16 + (lane >> 2);
            const int col = n0 + wn*WTN + nt*8 + (lane & 3)*2;
            #pragma unroll
            for (int h = 0; h < 2; ++h) {
                const int r2 = row + h*8;
                float v0 = acc[mt][nt][h*2+0] * alpha;
                float v1 = acc[mt][nt][h*2+1] * alpha;
                if (bias) { v0 += bias[col]; v1 += bias[col+1]; }
                if (EPI == 1) {
                    const float2 rv = *(const float2*)(R + (size_t)r2*ldr + col);
                    v0 += rv.x; v1 += rv.y;
                }
                if (EPI == 2) {
                    v0 = 0.5f*v0*(1.0f + erff(v0 * 0.70710678118654752f));
                    v1 = 0.5f*v1*(1.0f + erff(v1 * 0.70710678118654752f));
                }
                *(float2*)(C + (size_t)r2*ldc + col) = make_float2(v0, v1);
            }
        }
    }
}

// ---------------------------------------------------------------------------
// Softmax over rows of length 512 (warp per row)
// ---------------------------------------------------------------------------
__global__ void softmax512(float* __restrict__ P, int rows)
{
    const int warp = (blockIdx.x * blockDim.x + threadIdx.x) >> 5;
    const int lane = threadIdx.x & 31;
    if (warp >= rows) return;
    float4* p = (float4*)(P + (size_t)warp * 512);

    float4 v[4];
    float mx = -3.4e38f;
    #pragma unroll
    for (int i = 0; i < 4; ++i) {
        v[i] = p[lane + i*32];
        mx = fmaxf(mx, fmaxf(fmaxf(v[i].x, v[i].y), fmaxf(v[i].z, v[i].w)));
    }
    #pragma unroll
    for (int o = 16; o; o >>= 1) mx = fmaxf(mx, __shfl_xor_sync(0xffffffffu, mx, o));

    float s = 0.0f;
    #pragma unroll
    for (int i = 0; i < 4; ++i) {
        v[i].x = expf(v[i].x - mx); v[i].y = expf(v[i].y - mx);
        v[i].z = expf(v[i].z - mx); v[i].w = expf(v[i].w - mx);
        s += v[i].x + v[i].y + v[i].z + v[i].w;
    }
    #pragma unroll
    for (int o = 16; o; o >>= 1) s += __shfl_xor_sync(0xffffffffu, s, o);
    const float inv = 1.0f / s;
    #pragma unroll
    for (int i = 0; i < 4; ++i) {
        v[i].x *= inv; v[i].y *= inv; v[i].z *= inv; v[i].w *= inv;
        p[lane + i*32] = v[i];
    }
}

// ---------------------------------------------------------------------------
// LayerNorm over rows of length 768 (warp per row)
// ---------------------------------------------------------------------------
__global__ void layernorm768(const float* __restrict__ X,
                             const float* __restrict__ g,
                             const float* __restrict__ b,
                             float* __restrict__ Y, int rows)
{
    const int warp = (blockIdx.x * blockDim.x + threadIdx.x) >> 5;
    const int lane = threadIdx.x & 31;
    if (warp >= rows) return;
    const float4* x = (const float4*)(X + (size_t)warp * 768);

    float4 v[6];
    float s = 0.0f;
    #pragma unroll
    for (int i = 0; i < 6; ++i) {
        v[i] = x[lane + i*32];
        s += v[i].x + v[i].y + v[i].z + v[i].w;
    }
    #pragma unroll
    for (int o = 16; o; o >>= 1) s += __shfl_xor_sync(0xffffffffu, s, o);
    const float mean = s * (1.0f / 768.0f);

    float var = 0.0f;
    #pragma unroll
    for (int i = 0; i < 6; ++i) {
        float dx = v[i].x - mean, dy = v[i].y - mean, dz = v[i].z - mean, dw = v[i].w - mean;
        var += dx*dx + dy*dy + dz*dz + dw*dw;
    }
    #pragma unroll
    for (int o = 16; o; o >>= 1) var += __shfl_xor_sync(0xffffffffu, var, o);
    const float rs = rsqrtf(var * (1.0f / 768.0f) + 1e-12f);

    float4* y = (float4*)(Y + (size_t)warp * 768);
    const float4* gg = (const float4*)g;
    const float4* bb = (const float4*)b;
    #pragma unroll
    for (int i = 0; i < 6; ++i) {
        const int c = lane + i*32;
        const float4 gv = gg[c], bv = bb[c];
        float4 o4;
        o4.x = (v[i].x - mean) * rs * gv.x + bv.x;
        o4.y = (v[i].y - mean) * rs * gv.y + bv.y;
        o4.z = (v[i].z - mean) * rs * gv.z + bv.z;
        o4.w = (v[i].w - mean) * rs * gv.w + bv.w;
        y[c] = o4;
    }
}

// ---------------------------------------------------------------------------
// Launch
// ---------------------------------------------------------------------------
extern "C" void kernel_launch(void* const* d_in, const int* in_sizes, int n_in,
                              void* d_out, int out_size)
{
    (void)in_sizes; (void)n_in; (void)out_size;
    const float* hs  = (const float*)d_in[0];
    const float* Wq  = (const float*)d_in[1];  const float* bq  = (const float*)d_in[2];
    const float* Wk  = (const float*)d_in[3];  const float* bk  = (const float*)d_in[4];
    const float* Wv  = (const float*)d_in[5];  const float* bv  = (const float*)d_in[6];
    const float* Wo  = (const float*)d_in[7];  const float* bo  = (const float*)d_in[8];
    const float* g1  = (const float*)d_in[9];  const float* b1  = (const float*)d_in[10];
    const float* Wi  = (const float*)d_in[11]; const float* bi  = (const float*)d_in[12];
    const float* Wo2 = (const float*)d_in[13]; const float* bo2 = (const float*)d_in[14];
    const float* g2  = (const float*)d_in[15]; const float* b2  = (const float*)d_in[16];

    float *X, *Q, *Kb, *V, *P, *Cx, *T, *Aa, *Ib;
    cudaGetSymbolAddress((void**)&X,  g_X);
    cudaGetSymbolAddress((void**)&Q,  g_Q);
    cudaGetSymbolAddress((void**)&Kb, g_K);
    cudaGetSymbolAddress((void**)&V,  g_V);
    cudaGetSymbolAddress((void**)&P,  g_P);
    cudaGetSymbolAddress((void**)&Cx, g_C);
    cudaGetSymbolAddress((void**)&T,  g_T);
    cudaGetSymbolAddress((void**)&Aa, g_A);
    cudaGetSymbolAddress((void**)&Ib, g_I);

    cudaMemcpyAsync(X, hs, sizeof(float)*(size_t)M0*HH, cudaMemcpyDeviceToDevice, 0);

    const long long sQ1 = (long long)SS*HH;
    const long long sQ2 = DHH;
    const long long sP1 = (long long)NHH*SS*SS;
    const long long sP2 = (long long)SS*SS;

    for (int l = 0; l < LL; ++l) {
        const float* wq  = Wq  + (size_t)l*HH*HH; const float* bql  = bq  + (size_t)l*HH;
        const float* wk  = Wk  + (size_t)l*HH*HH; const float* bkl  = bk  + (size_t)l*HH;
        const float* wv  = Wv  + (size_t)l*HH*HH; const float* bvl  = bv  + (size_t)l*HH;
        const float* wo  = Wo  + (size_t)l*HH*HH; const float* bol  = bo  + (size_t)l*HH;
        const float* wi  = Wi  + (size_t)l*HH*II; const float* bil  = bi  + (size_t)l*II;
        const float* wo2 = Wo2 + (size_t)l*II*HH; const float* bo2l = bo2 + (size_t)l*HH;

        // Q, K, V projections: [8192,768] = X @ W + b
        dim3 gp(HH/128, M0/128, 1);
        gemm_mma<128,128,32,4,2,false,0><<<gp,256>>>(X,HH, wq,HH, bql, nullptr,0, Q ,HH,
            M0,HH,HH, 1.0f, 0,0,0,0,0,0, 1);
        gemm_mma<128,128,32,4,2,false,0><<<gp,256>>>(X,HH, wk,HH, bkl, nullptr,0, Kb,HH,
            M0,HH,HH, 1.0f, 0,0,0,0,0,0, 1);
        gemm_mma<128,128,32,4,2,false,0><<<gp,256>>>(X,HH, wv,HH, bvl, nullptr,0, V ,HH,
            M0,HH,HH, 1.0f, 0,0,0,0,0,0, 1);

        // scores[b,h] = Q_bh @ K_bh^T / 8   (M=N=512, K=64, 192 batches)
        dim3 gs(SS/128, SS/128, NBA);
        gemm_mma<128,128,32,4,2,true,0><<<gs,256>>>(Q,HH, Kb,HH, nullptr, nullptr,0, P,SS,
            SS,SS,DHH, 0.125f, sQ1,sQ2, sQ1,sQ2, sP1,sP2, NHH);

        softmax512<<<(NBA*SS)/8, 256>>>(P, NBA*SS);

        // ctx[b,h] = probs @ V_bh   (M=512, N=64, K=512)
        dim3 gc(1, SS/128, NBA);
        gemm_mma<128,64,32,4,2,false,0><<<gc,256>>>(P,SS, V,HH, nullptr, nullptr,0, Cx,HH,
            SS,DHH,SS, 1.0f, sP1,sP2, sQ1,sQ2, sQ1,sQ2, NHH);

        // O projection + residual: T = ctx @ Wo + bo + X
        gemm_mma<128,128,32,4,2,false,1><<<gp,256>>>(Cx,HH, wo,HH, bol, X,HH, T,HH,
            M0,HH,HH, 1.0f, 0,0,0,0,0,0, 1);
        layernorm768<<<M0/8,256>>>(T, g1 + (size_t)l*HH, b1 + (size_t)l*HH, Aa, M0);

        // FFN1: I = gelu(attn_out @ Wi + bi)
        dim3 gf1(II/128, M0/128, 1);
        gemm_mma<128,128,32,4,2,false,2><<<gf1,256>>>(Aa,HH, wi,II, bil, nullptr,0, Ib,II,
            M0,II,HH, 1.0f, 0,0,0,0,0,0, 1);

        // FFN2 + residual: T = I @ Wo2 + bo2 + attn_out
        gemm_mma<128,128,32,4,2,false,1><<<gp,256>>>(Ib,II, wo2,HH, bo2l, Aa,HH, T,HH,
            M0,HH,II, 1.0f, 0,0,0,0,0,0, 1);

        float* outX = (l == LL-1) ? (float*)d_out : X;
        layernorm768<<<M0/8,256>>>(T, g2 + (size_t)l*HH, b2 + (size_t)l*HH, outX, M0);
    }
}

// round 7
// speedup vs baseline: 2.7594x; 1.0986x over previous
#include <cuda_runtime.h>
#include <cuda_bf16.h>
#include <math.h>
#include <stdint.h>

// Problem constants
#define BB   16
#define SS   512
#define HH   768
#define II   3072
#define NHH  12
#define DHH  64
#define LL   6
#define M0   (BB*SS)       // 8192 tokens
#define NBA  (BB*NHH)      // 192 attention batches

// ---------------------------------------------------------------------------
// Scratch buffers
// ---------------------------------------------------------------------------
__device__ float g_X[M0*HH];
__device__ float g_Q[M0*HH];
__device__ float g_K[M0*HH];
__device__ float g_V[M0*HH];
__device__ float g_C[M0*HH];
__device__ float g_T[M0*HH];
__device__ float g_A[M0*HH];
__device__ float g_I[M0*II];

// ---------------------------------------------------------------------------
// PTX helpers
// ---------------------------------------------------------------------------
__device__ __forceinline__ uint32_t smem_u32(const void* p) {
    return (uint32_t)__cvta_generic_to_shared(p);
}
__device__ __forceinline__ void ldsm_x4(uint32_t* r, uint32_t a) {
    asm volatile("ldmatrix.sync.aligned.m8n8.x4.shared.b16 {%0,%1,%2,%3}, [%4];"
        : "=r"(r[0]), "=r"(r[1]), "=r"(r[2]), "=r"(r[3]) : "r"(a));
}
__device__ __forceinline__ void ldsm_x4t(uint32_t* r, uint32_t a) {
    asm volatile("ldmatrix.sync.aligned.m8n8.x4.trans.shared.b16 {%0,%1,%2,%3}, [%4];"
        : "=r"(r[0]), "=r"(r[1]), "=r"(r[2]), "=r"(r[3]) : "r"(a));
}
__device__ __forceinline__ void mma16816(float* c, const uint32_t* a, const uint32_t* b) {
    asm volatile(
        "mma.sync.aligned.m16n8k16.row.col.f32.bf16.bf16.f32 "
        "{%0,%1,%2,%3}, {%4,%5,%6,%7}, {%8,%9}, {%0,%1,%2,%3};"
        : "+f"(c[0]), "+f"(c[1]), "+f"(c[2]), "+f"(c[3])
        : "r"(a[0]), "r"(a[1]), "r"(a[2]), "r"(a[3]), "r"(b[0]), "r"(b[1]));
}

// fp32 -> (bf16 hi, bf16 lo) exact-residual split
__device__ __forceinline__ void split1(float x, unsigned short& hi, unsigned short& lo) {
    __nv_bfloat16 h = __float2bfloat16(x);
    hi = *reinterpret_cast<unsigned short*>(&h);
    float r = x - __bfloat162float(h);
    __nv_bfloat16 l = __float2bfloat16(r);
    lo = *reinterpret_cast<unsigned short*>(&l);
}
__device__ __forceinline__ void split4(float4 v, ushort4& hi, ushort4& lo) {
    split1(v.x, hi.x, lo.x);
    split1(v.y, hi.y, lo.y);
    split1(v.z, hi.z, lo.z);
    split1(v.w, hi.w, lo.w);
}

// ---------------------------------------------------------------------------
// bf16x3 split-precision tensor-core GEMM, 2-stage smem pipeline.
//   C[M,N] = alpha * A[M,K] @ B[K,N] + bias + (residual | gelu)
// EPI: 0 = bias, 1 = bias + residual, 2 = bias + exact GELU
// ---------------------------------------------------------------------------
template<int BM, int BN, int BK, int WM, int WN, int EPI>
__global__ void __launch_bounds__(WM*WN*32)
gemm_mma(const float* __restrict__ A, int lda,
         const float* __restrict__ B, int ldb,
         const float* __restrict__ bias,
         const float* __restrict__ R, int ldr,
         float* __restrict__ C, int ldc,
         int K, float alpha)
{
    constexpr int THREADS = WM*WN*32;
    constexpr int WTM = BM/WM, WTN = BN/WN;
    constexpr int MT = WTM/16, NT = WTN/8;
    constexpr int PAD = 8;
    constexpr int LAS = BK+PAD, LBS = BN+PAD;
    constexpr int ASZ = BM*LAS, BSZ = BK*LBS;
    constexpr int STAGE = 2*ASZ + 2*BSZ;
    constexpr int AIT = BM*BK/4/THREADS;
    constexpr int BIT = BK*BN/4/THREADS;

    extern __shared__ __align__(16) unsigned short dynsm[];

    const int tid  = threadIdx.x;
    const int lane = tid & 31;
    const int wid  = tid >> 5;
    const int wm   = wid / WN;
    const int wn   = wid % WN;
    const int m0 = blockIdx.y * BM;
    const int n0 = blockIdx.x * BN;

    float acc[MT][NT][4] = {};
    float4 ra[AIT], rb[BIT];

    auto loadA = [&](int k0) {
        #pragma unroll
        for (int it = 0; it < AIT; ++it) {
            int id = tid + it*THREADS;
            int m  = id / (BK/4), kv = id % (BK/4);
            ra[it] = *(const float4*)(A + (size_t)(m0+m)*lda + k0 + kv*4);
        }
    };
    auto loadB = [&](int k0) {
        #pragma unroll
        for (int it = 0; it < BIT; ++it) {
            int id = tid + it*THREADS;
            int kk = id / (BN/4), nv = id % (BN/4);
            rb[it] = *(const float4*)(B + (size_t)(k0+kk)*ldb + n0 + nv*4);
        }
    };
    auto storeAB = [&](int st) {
        unsigned short* Ah = dynsm + st*STAGE;
        unsigned short* Al = Ah + ASZ;
        unsigned short* Bh = Al + ASZ;
        unsigned short* Bl = Bh + BSZ;
        #pragma unroll
        for (int it = 0; it < AIT; ++it) {
            int id = tid + it*THREADS;
            int m  = id / (BK/4), kv = id % (BK/4);
            ushort4 hi, lo; split4(ra[it], hi, lo);
            *(ushort4*)&Ah[m*LAS + kv*4] = hi;
            *(ushort4*)&Al[m*LAS + kv*4] = lo;
        }
        #pragma unroll
        for (int it = 0; it < BIT; ++it) {
            int id = tid + it*THREADS;
            int kk = id / (BN/4), nv = id % (BN/4);
            ushort4 hi, lo; split4(rb[it], hi, lo);
            *(ushort4*)&Bh[kk*LBS + nv*4] = hi;
            *(ushort4*)&Bl[kk*LBS + nv*4] = lo;
        }
    };

    const int nk = K / BK;
    loadA(0); loadB(0);
    storeAB(0);
    __syncthreads();

    for (int kt = 0; kt < nk; ++kt) {
        const int cur = kt & 1;
        if (kt + 1 < nk) { loadA((kt+1)*BK); loadB((kt+1)*BK); }

        const unsigned short* Ah = dynsm + cur*STAGE;
        const unsigned short* Al = Ah + ASZ;
        const unsigned short* Bh = Al + ASZ;
        const unsigned short* Bl = Bh + BSZ;

        #pragma unroll
        for (int ks = 0; ks < BK/16; ++ks) {
            uint32_t ah[MT][4], al[MT][4];
            #pragma unroll
            for (int mt = 0; mt < MT; ++mt) {
                int r = wm*WTM + mt*16 + (lane & 15);
                int c = ks*16 + ((lane >> 4) << 3);
                ldsm_x4(ah[mt], smem_u32(Ah + r*LAS + c));
                ldsm_x4(al[mt], smem_u32(Al + r*LAS + c));
            }
            #pragma unroll
            for (int np = 0; np < NT/2; ++np) {
                uint32_t bh[4], bl[4];
                int off = (ks*16 + (lane & 15))*LBS + wn*WTN + np*16 + ((lane >> 4) << 3);
                ldsm_x4t(bh, smem_u32(Bh + off));
                ldsm_x4t(bl, smem_u32(Bl + off));
                #pragma unroll
                for (int s = 0; s < 2; ++s) {
                    const int nt = np*2 + s;
                    #pragma unroll
                    for (int mt = 0; mt < MT; ++mt) {
                        mma16816(acc[mt][nt], ah[mt], bh + s*2);
                        mma16816(acc[mt][nt], al[mt], bh + s*2);
                        mma16816(acc[mt][nt], ah[mt], bl + s*2);
                    }
                }
            }
        }
        if (kt + 1 < nk) storeAB((kt+1) & 1);
        __syncthreads();
    }

    // --- epilogue ---
    #pragma unroll
    for (int mt = 0; mt < MT; ++mt) {
        #pragma unroll
        for (int nt = 0; nt < NT; ++nt) {
            const int row = m0 + wm*WTM + mt*16 + (lane >> 2);
            const int col = n0 + wn*WTN + nt*8 + (lane & 3)*2;
            #pragma unroll
            for (int h = 0; h < 2; ++h) {
                const int r2 = row + h*8;
                float v0 = acc[mt][nt][h*2+0] * alpha;
                float v1 = acc[mt][nt][h*2+1] * alpha;
                if (bias) { v0 += bias[col]; v1 += bias[col+1]; }
                if (EPI == 1) {
                    const float2 rv = *(const float2*)(R + (size_t)r2*ldr + col);
                    v0 += rv.x; v1 += rv.y;
                }
                if (EPI == 2) {
                    v0 = 0.5f*v0*(1.0f + erff(v0 * 0.70710678118654752f));
                    v1 = 0.5f*v1*(1.0f + erff(v1 * 0.70710678118654752f));
                }
                *(float2*)(C + (size_t)r2*ldc + col) = make_float2(v0, v1);
            }
        }
    }
}

// ---------------------------------------------------------------------------
// Fused flash attention: scores -> softmax -> ctx, all on-chip.
// Grid: (4 q-tiles, 192 b*h). Block: 256 threads (8 warps).
// Warp w owns Q rows [w*16, w*16+16) of its 128-row tile.
// Q/K/V loaded as split bf16 (hi/lo) in smem; bf16x3 MMAs for both GEMMs.
// ---------------------------------------------------------------------------
__global__ void __launch_bounds__(256, 1)
flash_attn(const float* __restrict__ Qg, const float* __restrict__ Kg,
           const float* __restrict__ Vg, float* __restrict__ Og)
{
    constexpr int DP  = DHH + 8;     // 72
    constexpr int QSZ = 128*DP;      // per hi/lo matrix

    extern __shared__ __align__(16) unsigned short dynsm[];
    unsigned short* Qh = dynsm;
    unsigned short* Ql = Qh + QSZ;
    unsigned short* Kh = Ql + QSZ;
    unsigned short* Kl = Kh + QSZ;
    unsigned short* Vh = Kl + QSZ;
    unsigned short* Vl = Vh + QSZ;

    const int tid = threadIdx.x, lane = tid & 31, w = tid >> 5;
    const int b = blockIdx.y / NHH, hh = blockIdx.y % NHH;
    const int q0 = blockIdx.x * 128;
    const float* Qp = Qg + (size_t)b*SS*HH + (size_t)q0*HH + hh*DHH;
    const float* Kp = Kg + (size_t)b*SS*HH + hh*DHH;
    const float* Vp = Vg + (size_t)b*SS*HH + hh*DHH;

    // --- load Q tile [128,64] (8 float4 per thread) ---
    #pragma unroll
    for (int it = 0; it < 8; ++it) {
        int id = tid + it*256;
        int r = id >> 4, c4 = id & 15;
        float4 v = *(const float4*)(Qp + (size_t)r*HH + c4*4);
        ushort4 hi, lo; split4(v, hi, lo);
        *(ushort4*)&Qh[r*DP + c4*4] = hi;
        *(ushort4*)&Ql[r*DP + c4*4] = lo;
    }
    __syncthreads();

    // --- hoist Q A-fragments (held for whole kernel) ---
    uint32_t qh[4][4], ql[4][4];
    {
        int r = w*16 + (lane & 15);
        #pragma unroll
        for (int ks = 0; ks < 4; ++ks) {
            int c = ks*16 + ((lane >> 4) << 3);
            ldsm_x4(qh[ks], smem_u32(Qh + r*DP + c));
            ldsm_x4(ql[ks], smem_u32(Ql + r*DP + c));
        }
    }

    float oacc[8][4] = {};
    float mrow[2] = {-1e30f, -1e30f};
    float lrow[2] = {0.0f, 0.0f};

    // Non-trans ldmatrix B-fragment addressing for K[n=seq][k=dh]:
    // m0/m1 -> rows n0..n0+7 (k 0-7 / 8-15), m2/m3 -> rows n0+8..15.
    const int kb_row = (lane & 7) + ((lane & 16) >> 1);
    const int kb_col = ((lane >> 3) & 1) * 8;

    for (int j = 0; j < 4; ++j) {
        const int s0 = j*128;
        // --- load K,V tiles [128,64] (straight, row-major, ushort4) ---
        #pragma unroll
        for (int it = 0; it < 8; ++it) {
            int id = tid + it*256;
            int r = id >> 4, c4 = id & 15;
            ushort4 hi, lo;
            float4 kv = *(const float4*)(Kp + (size_t)(s0+r)*HH + c4*4);
            split4(kv, hi, lo);
            *(ushort4*)&Kh[r*DP + c4*4] = hi;
            *(ushort4*)&Kl[r*DP + c4*4] = lo;
            float4 vv = *(const float4*)(Vp + (size_t)(s0+r)*HH + c4*4);
            split4(vv, hi, lo);
            *(ushort4*)&Vh[r*DP + c4*4] = hi;
            *(ushort4*)&Vl[r*DP + c4*4] = lo;
        }
        __syncthreads();

        // --- S = Q @ K^T (warp tile 16x128), bf16x3 ---
        float sacc[16][4] = {};
        #pragma unroll
        for (int ks = 0; ks < 4; ++ks) {
            #pragma unroll
            for (int np = 0; np < 8; ++np) {
                uint32_t bh[4], bl[4];
                int off = (np*16 + kb_row)*DP + ks*16 + kb_col;
                ldsm_x4(bh, smem_u32(Kh + off));
                ldsm_x4(bl, smem_u32(Kl + off));
                #pragma unroll
                for (int s = 0; s < 2; ++s) {
                    int nt = np*2 + s;
                    mma16816(sacc[nt], qh[ks], bh + s*2);
                    mma16816(sacc[nt], ql[ks], bh + s*2);
                    mma16816(sacc[nt], qh[ks], bl + s*2);
                }
            }
        }
        #pragma unroll
        for (int nt = 0; nt < 16; ++nt) {
            sacc[nt][0] *= 0.125f; sacc[nt][1] *= 0.125f;
            sacc[nt][2] *= 0.125f; sacc[nt][3] *= 0.125f;
        }

        // --- online softmax (rows are warp-local; 4-lane group holds a row) ---
        #pragma unroll
        for (int h = 0; h < 2; ++h) {
            float mx = -1e30f;
            #pragma unroll
            for (int nt = 0; nt < 16; ++nt)
                mx = fmaxf(mx, fmaxf(sacc[nt][2*h], sacc[nt][2*h+1]));
            mx = fmaxf(mx, __shfl_xor_sync(0xffffffffu, mx, 1));
            mx = fmaxf(mx, __shfl_xor_sync(0xffffffffu, mx, 2));
            float mnew = fmaxf(mrow[h], mx);
            float corr = expf(mrow[h] - mnew);
            mrow[h] = mnew;
            float sum = 0.0f;
            #pragma unroll
            for (int nt = 0; nt < 16; ++nt) {
                float p0 = expf(sacc[nt][2*h]   - mnew);
                float p1 = expf(sacc[nt][2*h+1] - mnew);
                sacc[nt][2*h] = p0; sacc[nt][2*h+1] = p1;
                sum += p0 + p1;
            }
            sum += __shfl_xor_sync(0xffffffffu, sum, 1);
            sum += __shfl_xor_sync(0xffffffffu, sum, 2);
            lrow[h] = lrow[h]*corr + sum;
            #pragma unroll
            for (int nt = 0; nt < 8; ++nt) {
                oacc[nt][2*h]   *= corr;
                oacc[nt][2*h+1] *= corr;
            }
        }

        // --- O += P @ V, bf16x3 (P repacked C-frag -> A-frag) ---
        #pragma unroll
        for (int ks = 0; ks < 8; ++ks) {
            uint32_t ph[4], pl[4];
            #pragma unroll
            for (int q = 0; q < 2; ++q) {
                #pragma unroll
                for (int hf = 0; hf < 2; ++hf) {
                    float x = sacc[2*ks+q][2*hf];
                    float y = sacc[2*ks+q][2*hf+1];
                    unsigned short hx, lx, hy, ly;
                    split1(x, hx, lx); split1(y, hy, ly);
                    ph[2*q+hf] = (uint32_t)hx | ((uint32_t)hy << 16);
                    pl[2*q+hf] = (uint32_t)lx | ((uint32_t)ly << 16);
                }
            }
            #pragma unroll
            for (int np = 0; np < 4; ++np) {
                uint32_t bh[4], bl[4];
                int off = (ks*16 + (lane & 15))*DP + np*16 + ((lane >> 4) << 3);
                ldsm_x4t(bh, smem_u32(Vh + off));
                ldsm_x4t(bl, smem_u32(Vl + off));
                #pragma unroll
                for (int s = 0; s < 2; ++s) {
                    int nt = np*2 + s;
                    mma16816(oacc[nt], ph, bh + s*2);
                    mma16816(oacc[nt], pl, bh + s*2);
                    mma16816(oacc[nt], ph, bl + s*2);
                }
            }
        }
        __syncthreads();
    }

    // --- write ctx = O / l ---
    float* Op = Og + (size_t)b*SS*HH + hh*DHH;
    const int orow = w*16 + (lane >> 2);
    #pragma unroll
    for (int h = 0; h < 2; ++h) {
        const float inv = 1.0f / lrow[h];
        const int r = q0 + orow + h*8;
        #pragma unroll
        for (int nt = 0; nt < 8; ++nt) {
            const int c = nt*8 + (lane & 3)*2;
            *(float2*)(Op + (size_t)r*HH + c) =
                make_float2(oacc[nt][2*h]*inv, oacc[nt][2*h+1]*inv);
        }
    }
}

// ---------------------------------------------------------------------------
// LayerNorm over rows of length 768 (warp per row)
// ---------------------------------------------------------------------------
__global__ void layernorm768(const float* __restrict__ X,
                             const float* __restrict__ g,
                             const float* __restrict__ b,
                             float* __restrict__ Y, int rows)
{
    const int warp = (blockIdx.x * blockDim.x + threadIdx.x) >> 5;
    const int lane = threadIdx.x & 31;
    if (warp >= rows) return;
    const float4* x = (const float4*)(X + (size_t)warp * 768);

    float4 v[6];
    float s = 0.0f;
    #pragma unroll
    for (int i = 0; i < 6; ++i) {
        v[i] = x[lane + i*32];
        s += v[i].x + v[i].y + v[i].z + v[i].w;
    }
    #pragma unroll
    for (int o = 16; o; o >>= 1) s += __shfl_xor_sync(0xffffffffu, s, o);
    const float mean = s * (1.0f / 768.0f);

    float var = 0.0f;
    #pragma unroll
    for (int i = 0; i < 6; ++i) {
        float dx = v[i].x - mean, dy = v[i].y - mean, dz = v[i].z - mean, dw = v[i].w - mean;
        var += dx*dx + dy*dy + dz*dz + dw*dw;
    }
    #pragma unroll
    for (int o = 16; o; o >>= 1) var += __shfl_xor_sync(0xffffffffu, var, o);
    const float rs = rsqrtf(var * (1.0f / 768.0f) + 1e-12f);

    float4* y = (float4*)(Y + (size_t)warp * 768);
    const float4* gg = (const float4*)g;
    const float4* bb = (const float4*)b;
    #pragma unroll
    for (int i = 0; i < 6; ++i) {
        const int c = lane + i*32;
        const float4 gv = gg[c], bv = bb[c];
        float4 o4;
        o4.x = (v[i].x - mean) * rs * gv.x + bv.x;
        o4.y = (v[i].y - mean) * rs * gv.y + bv.y;
        o4.z = (v[i].z - mean) * rs * gv.z + bv.z;
        o4.w = (v[i].w - mean) * rs * gv.w + bv.w;
        y[c] = o4;
    }
}

// ---------------------------------------------------------------------------
// Launch
// ---------------------------------------------------------------------------
#define GEMM_SMEM ((2*(128*(32+8)) + 2*(32*(128+8))) * 2 * 2)   // 75776 B
#define FLASH_SMEM (6*128*(64+8)*2)                              // 110592 B

extern "C" void kernel_launch(void* const* d_in, const int* in_sizes, int n_in,
                              void* d_out, int out_size)
{
    (void)in_sizes; (void)n_in; (void)out_size;
    const float* hs  = (const float*)d_in[0];
    const float* Wq  = (const float*)d_in[1];  const float* bq  = (const float*)d_in[2];
    const float* Wk  = (const float*)d_in[3];  const float* bk  = (const float*)d_in[4];
    const float* Wv  = (const float*)d_in[5];  const float* bv  = (const float*)d_in[6];
    const float* Wo  = (const float*)d_in[7];  const float* bo  = (const float*)d_in[8];
    const float* g1  = (const float*)d_in[9];  const float* b1  = (const float*)d_in[10];
    const float* Wi  = (const float*)d_in[11]; const float* bi  = (const float*)d_in[12];
    const float* Wo2 = (const float*)d_in[13]; const float* bo2 = (const float*)d_in[14];
    const float* g2  = (const float*)d_in[15]; const float* b2  = (const float*)d_in[16];

    float *X, *Q, *Kb, *V, *Cx, *T, *Aa, *Ib;
    cudaGetSymbolAddress((void**)&X,  g_X);
    cudaGetSymbolAddress((void**)&Q,  g_Q);
    cudaGetSymbolAddress((void**)&Kb, g_K);
    cudaGetSymbolAddress((void**)&V,  g_V);
    cudaGetSymbolAddress((void**)&Cx, g_C);
    cudaGetSymbolAddress((void**)&T,  g_T);
    cudaGetSymbolAddress((void**)&Aa, g_A);
    cudaGetSymbolAddress((void**)&Ib, g_I);

    cudaFuncSetAttribute(gemm_mma<128,128,32,4,2,0>,
        cudaFuncAttributeMaxDynamicSharedMemorySize, GEMM_SMEM);
    cudaFuncSetAttribute(gemm_mma<128,128,32,4,2,1>,
        cudaFuncAttributeMaxDynamicSharedMemorySize, GEMM_SMEM);
    cudaFuncSetAttribute(gemm_mma<128,128,32,4,2,2>,
        cudaFuncAttributeMaxDynamicSharedMemorySize, GEMM_SMEM);
    cudaFuncSetAttribute(flash_attn,
        cudaFuncAttributeMaxDynamicSharedMemorySize, FLASH_SMEM);

    cudaMemcpyAsync(X, hs, sizeof(float)*(size_t)M0*HH, cudaMemcpyDeviceToDevice, 0);

    for (int l = 0; l < LL; ++l) {
        const float* wq  = Wq  + (size_t)l*HH*HH; const float* bql  = bq  + (size_t)l*HH;
        const float* wk  = Wk  + (size_t)l*HH*HH; const float* bkl  = bk  + (size_t)l*HH;
        const float* wv  = Wv  + (size_t)l*HH*HH; const float* bvl  = bv  + (size_t)l*HH;
        const float* wo  = Wo  + (size_t)l*HH*HH; const float* bol  = bo  + (size_t)l*HH;
        const float* wi  = Wi  + (size_t)l*HH*II; const float* bil  = bi  + (size_t)l*II;
        const float* wo2 = Wo2 + (size_t)l*II*HH; const float* bo2l = bo2 + (size_t)l*HH;

        // Q, K, V projections: [8192,768] = X @ W + b
        dim3 gp(HH/128, M0/128, 1);
        gemm_mma<128,128,32,4,2,0><<<gp,256,GEMM_SMEM>>>(X,HH, wq,HH, bql, nullptr,0, Q ,HH, HH, 1.0f);
        gemm_mma<128,128,32,4,2,0><<<gp,256,GEMM_SMEM>>>(X,HH, wk,HH, bkl, nullptr,0, Kb,HH, HH, 1.0f);
        gemm_mma<128,128,32,4,2,0><<<gp,256,GEMM_SMEM>>>(X,HH, wv,HH, bvl, nullptr,0, V ,HH, HH, 1.0f);

        // fused attention: scores + softmax + ctx
        flash_attn<<<dim3(SS/128, NBA), 256, FLASH_SMEM>>>(Q, Kb, V, Cx);

        // O projection + residual: T = ctx @ Wo + bo + X
        gemm_mma<128,128,32,4,2,1><<<gp,256,GEMM_SMEM>>>(Cx,HH, wo,HH, bol, X,HH, T,HH, HH, 1.0f);
        layernorm768<<<M0/8,256>>>(T, g1 + (size_t)l*HH, b1 + (size_t)l*HH, Aa, M0);

        // FFN1: I = gelu(attn_out @ Wi + bi)
        dim3 gf1(II/128, M0/128, 1);
        gemm_mma<128,128,32,4,2,2><<<gf1,256,GEMM_SMEM>>>(Aa,HH, wi,II, bil, nullptr,0, Ib,II, HH, 1.0f);

        // FFN2 + residual: T = I @ Wo2 + bo2 + attn_out
        gemm_mma<128,128,32,4,2,1><<<gp,256,GEMM_SMEM>>>(Ib,II, wo2,HH, bo2l, Aa,HH, T,HH, II, 1.0f);

        float* outX = (l == LL-1) ? (float*)d_out : X;
        layernorm768<<<M0/8,256>>>(T, g2 + (size_t)l*HH, b2 + (size_t)l*HH, outX, M0);
    }
}

// round 9
// speedup vs baseline: 2.9554x; 1.0710x over previous
#include <cuda_runtime.h>
#include <cuda_bf16.h>
#include <math.h>
#include <stdint.h>

// Problem constants
#define BB   16
#define SS   512
#define HH   768
#define II   3072
#define NHH  12
#define DHH  64
#define LL   6
#define M0   (BB*SS)       // 8192 tokens
#define NBA  (BB*NHH)      // 192 attention batches
#define H3   (3*HH)        // 2304

// ---------------------------------------------------------------------------
// Scratch buffers
// ---------------------------------------------------------------------------
__device__ float g_X[M0*HH];
__device__ float g_QKV[M0*H3];        // fused Q|K|V, row stride 2304
__device__ float g_C[M0*HH];
__device__ float g_T[M0*HH];
__device__ float g_A[M0*HH];
__device__ float g_I[M0*II];
// pre-split bf16 weights (hi/lo residual pairs), original [K][N] layout
__device__ __nv_bfloat16 g_WqkvH[LL*HH*H3];
__device__ __nv_bfloat16 g_WqkvL[LL*HH*H3];
__device__ __nv_bfloat16 g_WoH[LL*HH*HH];
__device__ __nv_bfloat16 g_WoL[LL*HH*HH];
__device__ __nv_bfloat16 g_WiH[LL*HH*II];
__device__ __nv_bfloat16 g_WiL[LL*HH*II];
__device__ __nv_bfloat16 g_Wo2H[LL*II*HH];
__device__ __nv_bfloat16 g_Wo2L[LL*II*HH];
__device__ float g_bqkv[LL*H3];

// ---------------------------------------------------------------------------
// PTX helpers
// ---------------------------------------------------------------------------
__device__ __forceinline__ uint32_t smem_u32(const void* p) {
    return (uint32_t)__cvta_generic_to_shared(p);
}
__device__ __forceinline__ void ldsm_x4(uint32_t* r, uint32_t a) {
    asm volatile("ldmatrix.sync.aligned.m8n8.x4.shared.b16 {%0,%1,%2,%3}, [%4];"
        : "=r"(r[0]), "=r"(r[1]), "=r"(r[2]), "=r"(r[3]) : "r"(a));
}
__device__ __forceinline__ void ldsm_x4t(uint32_t* r, uint32_t a) {
    asm volatile("ldmatrix.sync.aligned.m8n8.x4.trans.shared.b16 {%0,%1,%2,%3}, [%4];"
        : "=r"(r[0]), "=r"(r[1]), "=r"(r[2]), "=r"(r[3]) : "r"(a));
}
__device__ __forceinline__ void mma16816(float* c, const uint32_t* a, const uint32_t* b) {
    asm volatile(
        "mma.sync.aligned.m16n8k16.row.col.f32.bf16.bf16.f32 "
        "{%0,%1,%2,%3}, {%4,%5,%6,%7}, {%8,%9}, {%0,%1,%2,%3};"
        : "+f"(c[0]), "+f"(c[1]), "+f"(c[2]), "+f"(c[3])
        : "r"(a[0]), "r"(a[1]), "r"(a[2]), "r"(a[3]), "r"(b[0]), "r"(b[1]));
}

// fp32 -> (bf16 hi, bf16 lo) exact-residual split
__device__ __forceinline__ void split1(float x, unsigned short& hi, unsigned short& lo) {
    __nv_bfloat16 h = __float2bfloat16(x);
    hi = *reinterpret_cast<unsigned short*>(&h);
    float r = x - __bfloat162float(h);
    __nv_bfloat16 l = __float2bfloat16(r);
    lo = *reinterpret_cast<unsigned short*>(&l);
}
__device__ __forceinline__ void split4(float4 v, ushort4& hi, ushort4& lo) {
    split1(v.x, hi.x, lo.x);
    split1(v.y, hi.y, lo.y);
    split1(v.z, hi.z, lo.z);
    split1(v.w, hi.w, lo.w);
}

// ---------------------------------------------------------------------------
// Weight pre-split: src fp32 [L][R][C] -> (hi,lo) bf16 [L][R][outC] at colOff
// ---------------------------------------------------------------------------
__global__ void split_w(const float* __restrict__ src,
                        __nv_bfloat16* __restrict__ dh,
                        __nv_bfloat16* __restrict__ dl,
                        int R, int Cc, int outC, int colOff)
{
    const int l = blockIdx.y;
    const float* s = src + (size_t)l*R*Cc;
    __nv_bfloat16* ph = dh + (size_t)l*R*outC;
    __nv_bfloat16* pl = dl + (size_t)l*R*outC;
    int id = blockIdx.x*256 + threadIdx.x;
    if (id >= R*Cc/4) return;
    int r = id / (Cc/4), c4 = id % (Cc/4);
    float4 v = *(const float4*)(s + (size_t)r*Cc + c4*4);
    ushort4 hi, lo; split4(v, hi, lo);
    *(ushort4*)(ph + (size_t)r*outC + colOff + c4*4) = hi;
    *(ushort4*)(pl + (size_t)r*outC + colOff + c4*4) = lo;
}

__global__ void concat_bias(const float* __restrict__ bq, const float* __restrict__ bk,
                            const float* __restrict__ bv, float* __restrict__ dst)
{
    int id = blockIdx.x*256 + threadIdx.x;
    if (id >= LL*HH) return;
    int l = id / HH, c = id % HH;
    dst[(size_t)l*H3 + c]        = bq[id];
    dst[(size_t)l*H3 + HH + c]   = bk[id];
    dst[(size_t)l*H3 + 2*HH + c] = bv[id];
}

// ---------------------------------------------------------------------------
// bf16x3 split GEMM, 512 threads (16 warps, 4/SMSP), 2-stage smem pipeline.
//   C[M,N] = A[M,K](fp32, split in-kernel) @ B[K,N](pre-split bf16 hi/lo)
// EPI: 0 = bias, 1 = bias + residual, 2 = bias + exact GELU
// Block tile 128x128x32; warp tile 32x32 (4x4 warps).
// ---------------------------------------------------------------------------
#define GEMM_SMEM 75776

template<int EPI>
__global__ void __launch_bounds__(512)
gemm_bf3(const float* __restrict__ A, int lda,
         const __nv_bfloat16* __restrict__ BH,
         const __nv_bfloat16* __restrict__ BLo, int ldb,
         const float* __restrict__ bias,
         const float* __restrict__ R, int ldr,
         float* __restrict__ C, int ldc, int K)
{
    constexpr int BM = 128, BN = 128, BK = 32;
    constexpr int PAD = 8, LAS = BK+PAD, LBS = BN+PAD;
    constexpr int ASZ = BM*LAS, BSZ = BK*LBS;
    constexpr int STAGE = 2*ASZ + 2*BSZ;

    extern __shared__ __align__(16) unsigned short sm[];

    const int tid = threadIdx.x, lane = tid & 31, wid = tid >> 5;
    const int wm = wid >> 2, wn = wid & 3;       // 4x4 warp grid
    const int m0 = blockIdx.y * BM, n0 = blockIdx.x * BN;

    float acc[2][4][4] = {};
    float4 ra[2];
    uint4 rbh, rbl;

    auto loadA = [&](int k0) {
        #pragma unroll
        for (int it = 0; it < 2; ++it) {
            int id = tid + it*512, m = id >> 3, kv = id & 7;   // BK/4 = 8
            ra[it] = *(const float4*)(A + (size_t)(m0+m)*lda + k0 + kv*4);
        }
    };
    auto loadB = [&](int k0) {
        int kk = tid >> 4, nv = tid & 15;                       // BN/8 = 16
        rbh = *(const uint4*)(BH  + (size_t)(k0+kk)*ldb + n0 + nv*8);
        rbl = *(const uint4*)(BLo + (size_t)(k0+kk)*ldb + n0 + nv*8);
    };
    auto storeAB = [&](int st) {
        unsigned short* Ah = sm + st*STAGE;
        unsigned short* Al = Ah + ASZ;
        unsigned short* Bh = Al + ASZ;
        unsigned short* Bl = Bh + BSZ;
        #pragma unroll
        for (int it = 0; it < 2; ++it) {
            int id = tid + it*512, m = id >> 3, kv = id & 7;
            ushort4 hi, lo; split4(ra[it], hi, lo);
            *(ushort4*)&Ah[m*LAS + kv*4] = hi;
            *(ushort4*)&Al[m*LAS + kv*4] = lo;
        }
        int kk = tid >> 4, nv = tid & 15;
        *(uint4*)&Bh[kk*LBS + nv*8] = rbh;
        *(uint4*)&Bl[kk*LBS + nv*8] = rbl;
    };

    const int nk = K / BK;
    loadA(0); loadB(0);
    storeAB(0);
    __syncthreads();

    for (int kt = 0; kt < nk; ++kt) {
        const int cur = kt & 1;
        if (kt + 1 < nk) { loadA((kt+1)*BK); loadB((kt+1)*BK); }

        const unsigned short* Ah = sm + cur*STAGE;
        const unsigned short* Al = Ah + ASZ;
        const unsigned short* Bh = Al + ASZ;
        const unsigned short* Bl = Bh + BSZ;

        #pragma unroll
        for (int ks = 0; ks < 2; ++ks) {
            uint32_t ah[2][4], al[2][4];
            #pragma unroll
            for (int mt = 0; mt < 2; ++mt) {
                int r = wm*32 + mt*16 + (lane & 15);
                int c = ks*16 + ((lane >> 4) << 3);
                ldsm_x4(ah[mt], smem_u32(Ah + r*LAS + c));
                ldsm_x4(al[mt], smem_u32(Al + r*LAS + c));
            }
            #pragma unroll
            for (int np = 0; np < 2; ++np) {
                uint32_t bh[4], bl[4];
                int off = (ks*16 + (lane & 15))*LBS + wn*32 + np*16 + ((lane >> 4) << 3);
                ldsm_x4t(bh, smem_u32(Bh + off));
                ldsm_x4t(bl, smem_u32(Bl + off));
                #pragma unroll
                for (int s = 0; s < 2; ++s) {
                    const int nt = np*2 + s;
                    #pragma unroll
                    for (int mt = 0; mt < 2; ++mt) {
                        mma16816(acc[mt][nt], ah[mt], bh + s*2);
                        mma16816(acc[mt][nt], al[mt], bh + s*2);
                        mma16816(acc[mt][nt], ah[mt], bl + s*2);
                    }
                }
            }
        }
        if (kt + 1 < nk) storeAB((kt+1) & 1);
        __syncthreads();
    }

    // --- epilogue ---
    #pragma unroll
    for (int mt = 0; mt < 2; ++mt) {
        #pragma unroll
        for (int nt = 0; nt < 4; ++nt) {
            const int row = m0 + wm*32 + mt*16 + (lane >> 2);
            const int col = n0 + wn*32 + nt*8 + (lane & 3)*2;
            #pragma unroll
            for (int h = 0; h < 2; ++h) {
                const int r2 = row + h*8;
                float v0 = acc[mt][nt][h*2+0];
                float v1 = acc[mt][nt][h*2+1];
                if (bias) { v0 += bias[col]; v1 += bias[col+1]; }
                if (EPI == 1) {
                    const float2 rv = *(const float2*)(R + (size_t)r2*ldr + col);
                    v0 += rv.x; v1 += rv.y;
                }
                if (EPI == 2) {
                    v0 = 0.5f*v0*(1.0f + erff(v0 * 0.70710678118654752f));
                    v1 = 0.5f*v1*(1.0f + erff(v1 * 0.70710678118654752f));
                }
                *(float2*)(C + (size_t)r2*ldc + col) = make_float2(v0, v1);
            }
        }
    }
}

// ---------------------------------------------------------------------------
// Fused flash attention: Q/K/V read from strided QKV buffer (ld = 2304).
// Grid: (4 q-tiles, 192 b*h). Block: 256 threads (8 warps).
// ---------------------------------------------------------------------------
__global__ void __launch_bounds__(256, 1)
flash_attn(const float* __restrict__ Qg, const float* __restrict__ Kg,
           const float* __restrict__ Vg, int ld, float* __restrict__ Og)
{
    constexpr int DP  = DHH + 8;
    constexpr int QSZ = 128*DP;

    extern __shared__ __align__(16) unsigned short dynsm[];
    unsigned short* Qh = dynsm;
    unsigned short* Ql = Qh + QSZ;
    unsigned short* Kh = Ql + QSZ;
    unsigned short* Kl = Kh + QSZ;
    unsigned short* Vh = Kl + QSZ;
    unsigned short* Vl = Vh + QSZ;

    const int tid = threadIdx.x, lane = tid & 31, w = tid >> 5;
    const int b = blockIdx.y / NHH, hh = blockIdx.y % NHH;
    const int q0 = blockIdx.x * 128;
    const float* Qp = Qg + ((size_t)b*SS + q0)*ld + hh*DHH;
    const float* Kp = Kg + (size_t)b*SS*ld + hh*DHH;
    const float* Vp = Vg + (size_t)b*SS*ld + hh*DHH;

    #pragma unroll
    for (int it = 0; it < 8; ++it) {
        int id = tid + it*256;
        int r = id >> 4, c4 = id & 15;
        float4 v = *(const float4*)(Qp + (size_t)r*ld + c4*4);
        ushort4 hi, lo; split4(v, hi, lo);
        *(ushort4*)&Qh[r*DP + c4*4] = hi;
        *(ushort4*)&Ql[r*DP + c4*4] = lo;
    }
    __syncthreads();

    uint32_t qh[4][4], ql[4][4];
    {
        int r = w*16 + (lane & 15);
        #pragma unroll
        for (int ks = 0; ks < 4; ++ks) {
            int c = ks*16 + ((lane >> 4) << 3);
            ldsm_x4(qh[ks], smem_u32(Qh + r*DP + c));
            ldsm_x4(ql[ks], smem_u32(Ql + r*DP + c));
        }
    }

    float oacc[8][4] = {};
    float mrow[2] = {-1e30f, -1e30f};
    float lrow[2] = {0.0f, 0.0f};

    const int kb_row = (lane & 7) + ((lane & 16) >> 1);
    const int kb_col = ((lane >> 3) & 1) * 8;

    for (int j = 0; j < 4; ++j) {
        const int s0 = j*128;
        #pragma unroll
        for (int it = 0; it < 8; ++it) {
            int id = tid + it*256;
            int r = id >> 4, c4 = id & 15;
            ushort4 hi, lo;
            float4 kv = *(const float4*)(Kp + (size_t)(s0+r)*ld + c4*4);
            split4(kv, hi, lo);
            *(ushort4*)&Kh[r*DP + c4*4] = hi;
            *(ushort4*)&Kl[r*DP + c4*4] = lo;
            float4 vv = *(const float4*)(Vp + (size_t)(s0+r)*ld + c4*4);
            split4(vv, hi, lo);
            *(ushort4*)&Vh[r*DP + c4*4] = hi;
            *(ushort4*)&Vl[r*DP + c4*4] = lo;
        }
        __syncthreads();

        float sacc[16][4] = {};
        #pragma unroll
        for (int ks = 0; ks < 4; ++ks) {
            #pragma unroll
            for (int np = 0; np < 8; ++np) {
                uint32_t bh[4], bl[4];
                int off = (np*16 + kb_row)*DP + ks*16 + kb_col;
                ldsm_x4(bh, smem_u32(Kh + off));
                ldsm_x4(bl, smem_u32(Kl + off));
                #pragma unroll
                for (int s = 0; s < 2; ++s) {
                    int nt = np*2 + s;
                    mma16816(sacc[nt], qh[ks], bh + s*2);
                    mma16816(sacc[nt], ql[ks], bh + s*2);
                    mma16816(sacc[nt], qh[ks], bl + s*2);
                }
            }
        }
        #pragma unroll
        for (int nt = 0; nt < 16; ++nt) {
            sacc[nt][0] *= 0.125f; sacc[nt][1] *= 0.125f;
            sacc[nt][2] *= 0.125f; sacc[nt][3] *= 0.125f;
        }

        #pragma unroll
        for (int h = 0; h < 2; ++h) {
            float mx = -1e30f;
            #pragma unroll
            for (int nt = 0; nt < 16; ++nt)
                mx = fmaxf(mx, fmaxf(sacc[nt][2*h], sacc[nt][2*h+1]));
            mx = fmaxf(mx, __shfl_xor_sync(0xffffffffu, mx, 1));
            mx = fmaxf(mx, __shfl_xor_sync(0xffffffffu, mx, 2));
            float mnew = fmaxf(mrow[h], mx);
            float corr = expf(mrow[h] - mnew);
            mrow[h] = mnew;
            float sum = 0.0f;
            #pragma unroll
            for (int nt = 0; nt < 16; ++nt) {
                float p0 = expf(sacc[nt][2*h]   - mnew);
                float p1 = expf(sacc[nt][2*h+1] - mnew);
                sacc[nt][2*h] = p0; sacc[nt][2*h+1] = p1;
                sum += p0 + p1;
            }
            sum += __shfl_xor_sync(0xffffffffu, sum, 1);
            sum += __shfl_xor_sync(0xffffffffu, sum, 2);
            lrow[h] = lrow[h]*corr + sum;
            #pragma unroll
            for (int nt = 0; nt < 8; ++nt) {
                oacc[nt][2*h]   *= corr;
                oacc[nt][2*h+1] *= corr;
            }
        }

        #pragma unroll
        for (int ks = 0; ks < 8; ++ks) {
            uint32_t ph[4], pl[4];
            #pragma unroll
            for (int q = 0; q < 2; ++q) {
                #pragma unroll
                for (int hf = 0; hf < 2; ++hf) {
                    float x = sacc[2*ks+q][2*hf];
                    float y = sacc[2*ks+q][2*hf+1];
                    unsigned short hx, lx, hy, ly;
                    split1(x, hx, lx); split1(y, hy, ly);
                    ph[2*q+hf] = (uint32_t)hx | ((uint32_t)hy << 16);
                    pl[2*q+hf] = (uint32_t)lx | ((uint32_t)ly << 16);
                }
            }
            #pragma unroll
            for (int np = 0; np < 4; ++np) {
                uint32_t bh[4], bl[4];
                int off = (ks*16 + (lane & 15))*DP + np*16 + ((lane >> 4) << 3);
                ldsm_x4t(bh, smem_u32(Vh + off));
                ldsm_x4t(bl, smem_u32(Vl + off));
                #pragma unroll
                for (int s = 0; s < 2; ++s) {
                    int nt = np*2 + s;
                    mma16816(oacc[nt], ph, bh + s*2);
                    mma16816(oacc[nt], pl, bh + s*2);
                    mma16816(oacc[nt], ph, bl + s*2);
                }
            }
        }
        __syncthreads();
    }

    float* Op = Og + (size_t)b*SS*HH + hh*DHH;
    const int orow = w*16 + (lane >> 2);
    #pragma unroll
    for (int h = 0; h < 2; ++h) {
        const float inv = 1.0f / lrow[h];
        const int r = q0 + orow + h*8;
        #pragma unroll
        for (int nt = 0; nt < 8; ++nt) {
            const int c = nt*8 + (lane & 3)*2;
            *(float2*)(Op + (size_t)r*HH + c) =
                make_float2(oacc[nt][2*h]*inv, oacc[nt][2*h+1]*inv);
        }
    }
}

// ---------------------------------------------------------------------------
// LayerNorm over rows of length 768 (warp per row)
// ---------------------------------------------------------------------------
__global__ void layernorm768(const float* __restrict__ X,
                             const float* __restrict__ g,
                             const float* __restrict__ b,
                             float* __restrict__ Y, int rows)
{
    const int warp = (blockIdx.x * blockDim.x + threadIdx.x) >> 5;
    const int lane = threadIdx.x & 31;
    if (warp >= rows) return;
    const float4* x = (const float4*)(X + (size_t)warp * 768);

    float4 v[6];
    float s = 0.0f;
    #pragma unroll
    for (int i = 0; i < 6; ++i) {
        v[i] = x[lane + i*32];
        s += v[i].x + v[i].y + v[i].z + v[i].w;
    }
    #pragma unroll
    for (int o = 16; o; o >>= 1) s += __shfl_xor_sync(0xffffffffu, s, o);
    const float mean = s * (1.0f / 768.0f);

    float var = 0.0f;
    #pragma unroll
    for (int i = 0; i < 6; ++i) {
        float dx = v[i].x - mean, dy = v[i].y - mean, dz = v[i].z - mean, dw = v[i].w - mean;
        var += dx*dx + dy*dy + dz*dz + dw*dw;
    }
    #pragma unroll
    for (int o = 16; o; o >>= 1) var += __shfl_xor_sync(0xffffffffu, var, o);
    const float rs = rsqrtf(var * (1.0f / 768.0f) + 1e-12f);

    float4* y = (float4*)(Y + (size_t)warp * 768);
    const float4* gg = (const float4*)g;
    const float4* bb = (const float4*)b;
    #pragma unroll
    for (int i = 0; i < 6; ++i) {
        const int c = lane + i*32;
        const float4 gv = gg[c], bv = bb[c];
        float4 o4;
        o4.x = (v[i].x - mean) * rs * gv.x + bv.x;
        o4.y = (v[i].y - mean) * rs * gv.y + bv.y;
        o4.z = (v[i].z - mean) * rs * gv.z + bv.z;
        o4.w = (v[i].w - mean) * rs * gv.w + bv.w;
        y[c] = o4;
    }
}

// ---------------------------------------------------------------------------
// Launch
// ---------------------------------------------------------------------------
#define FLASH_SMEM (6*128*(64+8)*2)   // 110592 B

extern "C" void kernel_launch(void* const* d_in, const int* in_sizes, int n_in,
                              void* d_out, int out_size)
{
    (void)in_sizes; (void)n_in; (void)out_size;
    const float* hs  = (const float*)d_in[0];
    const float* Wq  = (const float*)d_in[1];  const float* bq  = (const float*)d_in[2];
    const float* Wk  = (const float*)d_in[3];  const float* bk  = (const float*)d_in[4];
    const float* Wv  = (const float*)d_in[5];  const float* bv  = (const float*)d_in[6];
    const float* Wo  = (const float*)d_in[7];  const float* bo  = (const float*)d_in[8];
    const float* g1  = (const float*)d_in[9];  const float* b1  = (const float*)d_in[10];
    const float* Wi  = (const float*)d_in[11]; const float* bi  = (const float*)d_in[12];
    const float* Wo2 = (const float*)d_in[13]; const float* bo2 = (const float*)d_in[14];
    const float* g2  = (const float*)d_in[15]; const float* b2  = (const float*)d_in[16];

    float *X, *QKV, *Cx, *T, *Aa, *Ib, *bqkv;
    __nv_bfloat16 *WqkvH, *WqkvL, *WoH, *WoL, *WiH, *WiL, *Wo2H, *Wo2L;
    cudaGetSymbolAddress((void**)&X,    g_X);
    cudaGetSymbolAddress((void**)&QKV,  g_QKV);
    cudaGetSymbolAddress((void**)&Cx,   g_C);
    cudaGetSymbolAddress((void**)&T,    g_T);
    cudaGetSymbolAddress((void**)&Aa,   g_A);
    cudaGetSymbolAddress((void**)&Ib,   g_I);
    cudaGetSymbolAddress((void**)&bqkv, g_bqkv);
    cudaGetSymbolAddress((void**)&WqkvH, g_WqkvH);
    cudaGetSymbolAddress((void**)&WqkvL, g_WqkvL);
    cudaGetSymbolAddress((void**)&WoH,   g_WoH);
    cudaGetSymbolAddress((void**)&WoL,   g_WoL);
    cudaGetSymbolAddress((void**)&WiH,   g_WiH);
    cudaGetSymbolAddress((void**)&WiL,   g_WiL);
    cudaGetSymbolAddress((void**)&Wo2H,  g_Wo2H);
    cudaGetSymbolAddress((void**)&Wo2L,  g_Wo2L);

    cudaFuncSetAttribute(gemm_bf3<0>, cudaFuncAttributeMaxDynamicSharedMemorySize, GEMM_SMEM);
    cudaFuncSetAttribute(gemm_bf3<1>, cudaFuncAttributeMaxDynamicSharedMemorySize, GEMM_SMEM);
    cudaFuncSetAttribute(gemm_bf3<2>, cudaFuncAttributeMaxDynamicSharedMemorySize, GEMM_SMEM);
    cudaFuncSetAttribute(flash_attn,  cudaFuncAttributeMaxDynamicSharedMemorySize, FLASH_SMEM);

    cudaMemcpyAsync(X, hs, sizeof(float)*(size_t)M0*HH, cudaMemcpyDeviceToDevice, 0);

    // --- pre-split all weights into bf16 hi/lo (QKV concatenated) ---
    {
        split_w<<<dim3(HH*HH/1024, LL), 256>>>(Wq,  WqkvH, WqkvL, HH, HH, H3, 0);
        split_w<<<dim3(HH*HH/1024, LL), 256>>>(Wk,  WqkvH, WqkvL, HH, HH, H3, HH);
        split_w<<<dim3(HH*HH/1024, LL), 256>>>(Wv,  WqkvH, WqkvL, HH, HH, H3, 2*HH);
        split_w<<<dim3(HH*HH/1024, LL), 256>>>(Wo,  WoH,   WoL,   HH, HH, HH, 0);
        split_w<<<dim3(HH*II/1024, LL), 256>>>(Wi,  WiH,   WiL,   HH, II, II, 0);
        split_w<<<dim3(II*HH/1024, LL), 256>>>(Wo2, Wo2H,  Wo2L,  II, HH, HH, 0);
        concat_bias<<<(LL*HH + 255)/256, 256>>>(bq, bk, bv, bqkv);
    }

    for (int l = 0; l < LL; ++l) {
        const __nv_bfloat16* wqkvH = WqkvH + (size_t)l*HH*H3;
        const __nv_bfloat16* wqkvL = WqkvL + (size_t)l*HH*H3;
        const __nv_bfloat16* woH   = WoH   + (size_t)l*HH*HH;
        const __nv_bfloat16* woL   = WoL   + (size_t)l*HH*HH;
        const __nv_bfloat16* wiH   = WiH   + (size_t)l*HH*II;
        const __nv_bfloat16* wiL   = WiL   + (size_t)l*HH*II;
        const __nv_bfloat16* wo2H  = Wo2H  + (size_t)l*II*HH;
        const __nv_bfloat16* wo2L  = Wo2L  + (size_t)l*II*HH;
        const float* bqkvl = bqkv + (size_t)l*H3;
        const float* bol   = bo   + (size_t)l*HH;
        const float* bil   = bi   + (size_t)l*II;
        const float* bo2l  = bo2  + (size_t)l*HH;

        // fused QKV projection: [8192,2304] = X @ Wqkv + bqkv
        gemm_bf3<0><<<dim3(H3/128, M0/128), 512, GEMM_SMEM>>>(
            X, HH, wqkvH, wqkvL, H3, bqkvl, nullptr, 0, QKV, H3, HH);

        // fused attention: scores + softmax + ctx
        flash_attn<<<dim3(SS/128, NBA), 256, FLASH_SMEM>>>(
            QKV, QKV + HH, QKV + 2*HH, H3, Cx);

        // O projection + residual: T = ctx @ Wo + bo + X
        gemm_bf3<1><<<dim3(HH/128, M0/128), 512, GEMM_SMEM>>>(
            Cx, HH, woH, woL, HH, bol, X, HH, T, HH, HH);
        layernorm768<<<M0/8, 256>>>(T, g1 + (size_t)l*HH, b1 + (size_t)l*HH, Aa, M0);

        // FFN1: I = gelu(attn_out @ Wi + bi)
        gemm_bf3<2><<<dim3(II/128, M0/128), 512, GEMM_SMEM>>>(
            Aa, HH, wiH, wiL, II, bil, nullptr, 0, Ib, II, HH);

        // FFN2 + residual: T = I @ Wo2 + bo2 + attn_out
        gemm_bf3<1><<<dim3(HH/128, M0/128), 512, GEMM_SMEM>>>(
            Ib, II, wo2H, wo2L, HH, bo2l, Aa, HH, T, HH, II);

        float* outX = (l == LL-1) ? (float*)d_out : X;
        layernorm768<<<M0/8, 256>>>(T, g2 + (size_t)l*HH, b2 + (size_t)l*HH, outX, M0);
    }
}

// round 10
// speedup vs baseline: 3.0353x; 1.0270x over previous
#include <cuda_runtime.h>
#include <cuda_bf16.h>
#include <math.h>
#include <stdint.h>

// Problem constants
#define BB   16
#define SS   512
#define HH   768
#define II   3072
#define NHH  12
#define DHH  64
#define LL   6
#define M0   (BB*SS)       // 8192 tokens
#define NBA  (BB*NHH)      // 192 attention batches
#define H3   (3*HH)        // 2304

// ---------------------------------------------------------------------------
// Scratch buffers (activations as bf16 hi/lo pairs; T fp32 for LayerNorm)
// ---------------------------------------------------------------------------
__device__ __nv_bfloat16 g_XH[M0*HH],   g_XL[M0*HH];
__device__ __nv_bfloat16 g_QKVH[M0*H3], g_QKVL[M0*H3];
__device__ __nv_bfloat16 g_CH[M0*HH],   g_CL[M0*HH];
__device__ __nv_bfloat16 g_AH[M0*HH],   g_AL[M0*HH];
__device__ __nv_bfloat16 g_IH[M0*II],   g_IL[M0*II];
__device__ float g_T[M0*HH];
// pre-split bf16 weights (hi/lo), original [K][N] layout
__device__ __nv_bfloat16 g_WqkvH[LL*HH*H3], g_WqkvL[LL*HH*H3];
__device__ __nv_bfloat16 g_WoH[LL*HH*HH],   g_WoL[LL*HH*HH];
__device__ __nv_bfloat16 g_WiH[LL*HH*II],   g_WiL[LL*HH*II];
__device__ __nv_bfloat16 g_Wo2H[LL*II*HH],  g_Wo2L[LL*II*HH];
__device__ float g_bqkv[LL*H3];

// ---------------------------------------------------------------------------
// PTX helpers
// ---------------------------------------------------------------------------
__device__ __forceinline__ uint32_t smem_u32(const void* p) {
    return (uint32_t)__cvta_generic_to_shared(p);
}
__device__ __forceinline__ void ldsm_x4(uint32_t* r, uint32_t a) {
    asm volatile("ldmatrix.sync.aligned.m8n8.x4.shared.b16 {%0,%1,%2,%3}, [%4];"
        : "=r"(r[0]), "=r"(r[1]), "=r"(r[2]), "=r"(r[3]) : "r"(a));
}
__device__ __forceinline__ void ldsm_x4t(uint32_t* r, uint32_t a) {
    asm volatile("ldmatrix.sync.aligned.m8n8.x4.trans.shared.b16 {%0,%1,%2,%3}, [%4];"
        : "=r"(r[0]), "=r"(r[1]), "=r"(r[2]), "=r"(r[3]) : "r"(a));
}
__device__ __forceinline__ void mma16816(float* c, const uint32_t* a, const uint32_t* b) {
    asm volatile(
        "mma.sync.aligned.m16n8k16.row.col.f32.bf16.bf16.f32 "
        "{%0,%1,%2,%3}, {%4,%5,%6,%7}, {%8,%9}, {%0,%1,%2,%3};"
        : "+f"(c[0]), "+f"(c[1]), "+f"(c[2]), "+f"(c[3])
        : "r"(a[0]), "r"(a[1]), "r"(a[2]), "r"(a[3]), "r"(b[0]), "r"(b[1]));
}
#define CP_ASYNC16(dst, src) \
    asm volatile("cp.async.cg.shared.global [%0], [%1], 16;" :: "r"(dst), "l"(src) : "memory")
#define CP_COMMIT() asm volatile("cp.async.commit_group;" ::: "memory")
#define CP_WAIT1()  asm volatile("cp.async.wait_group 1;" ::: "memory")

// fp32 -> (bf16 hi, bf16 lo) exact-residual split
__device__ __forceinline__ void split1(float x, unsigned short& hi, unsigned short& lo) {
    __nv_bfloat16 h = __float2bfloat16(x);
    hi = *reinterpret_cast<unsigned short*>(&h);
    float r = x - __bfloat162float(h);
    __nv_bfloat16 l = __float2bfloat16(r);
    lo = *reinterpret_cast<unsigned short*>(&l);
}
__device__ __forceinline__ void split4(float4 v, ushort4& hi, ushort4& lo) {
    split1(v.x, hi.x, lo.x);
    split1(v.y, hi.y, lo.y);
    split1(v.z, hi.z, lo.z);
    split1(v.w, hi.w, lo.w);
}
__device__ __forceinline__ float bf2f(unsigned short u) {
    __nv_bfloat16 h = *reinterpret_cast<__nv_bfloat16*>(&u);
    return __bfloat162float(h);
}

// ---------------------------------------------------------------------------
// Preprocessing kernels
// ---------------------------------------------------------------------------
__global__ void split_w(const float* __restrict__ src,
                        __nv_bfloat16* __restrict__ dh,
                        __nv_bfloat16* __restrict__ dl,
                        int R, int Cc, int outC, int colOff)
{
    const int l = blockIdx.y;
    const float* s = src + (size_t)l*R*Cc;
    __nv_bfloat16* ph = dh + (size_t)l*R*outC;
    __nv_bfloat16* pl = dl + (size_t)l*R*outC;
    int id = blockIdx.x*256 + threadIdx.x;
    if (id >= R*Cc/4) return;
    int r = id / (Cc/4), c4 = id % (Cc/4);
    float4 v = *(const float4*)(s + (size_t)r*Cc + c4*4);
    ushort4 hi, lo; split4(v, hi, lo);
    *(ushort4*)(ph + (size_t)r*outC + colOff + c4*4) = hi;
    *(ushort4*)(pl + (size_t)r*outC + colOff + c4*4) = lo;
}

__global__ void split_x(const float* __restrict__ src,
                        __nv_bfloat16* __restrict__ dh,
                        __nv_bfloat16* __restrict__ dl, int n4)
{
    int id = blockIdx.x*256 + threadIdx.x;
    if (id >= n4) return;
    float4 v = *(const float4*)(src + (size_t)id*4);
    ushort4 hi, lo; split4(v, hi, lo);
    *(ushort4*)(dh + (size_t)id*4) = hi;
    *(ushort4*)(dl + (size_t)id*4) = lo;
}

__global__ void concat_bias(const float* __restrict__ bq, const float* __restrict__ bk,
                            const float* __restrict__ bv, float* __restrict__ dst)
{
    int id = blockIdx.x*256 + threadIdx.x;
    if (id >= LL*HH) return;
    int l = id / HH, c = id % HH;
    dst[(size_t)l*H3 + c]        = bq[id];
    dst[(size_t)l*H3 + HH + c]   = bk[id];
    dst[(size_t)l*H3 + 2*HH + c] = bv[id];
}

// ---------------------------------------------------------------------------
// bf16x3 GEMM, all-bf16 operands via cp.async, 3-stage pipeline.
// 256 threads (8 warps, warp tile 32x64), 2 CTAs/SM.
//   C[M,N] = (AH+AL)[M,K] @ (BH+BL)[K,N] + bias + epi
// EPI: 0 = bias -> split out (CH,CL); 1 = bias + residual(RH+RL) -> fp32 Cf;
//      2 = bias + exact GELU -> split out (CH,CL)
// ---------------------------------------------------------------------------
#define LAS   40            // A row stride (shorts): 32 + 8 pad
#define LBS   136           // B row stride (shorts): 128 + 8 pad
#define ASZ   (128*LAS)     // 5120 shorts
#define BSZ   (32*LBS)      // 4352 shorts
#define STG   (2*ASZ + 2*BSZ)          // 18944 shorts = 37888 B
#define GEMM_SMEM (3*STG*2)            // 113664 B

template<int EPI>
__global__ void __launch_bounds__(256, 2)
gemm_cp(const __nv_bfloat16* __restrict__ AH, const __nv_bfloat16* __restrict__ AL, int lda,
        const __nv_bfloat16* __restrict__ BH, const __nv_bfloat16* __restrict__ BL, int ldb,
        const float* __restrict__ bias,
        const __nv_bfloat16* __restrict__ RH, const __nv_bfloat16* __restrict__ RL, int ldr,
        float* __restrict__ Cf,
        __nv_bfloat16* __restrict__ CH, __nv_bfloat16* __restrict__ CL,
        int ldc, int K)
{
    extern __shared__ __align__(16) unsigned short sm[];
    const uint32_t smb = smem_u32(sm);

    const int tid = threadIdx.x, lane = tid & 31, wid = tid >> 5;
    const int wm = wid >> 1, wn = wid & 1;          // 4x2 warp grid, tile 32x64
    const int m0 = blockIdx.y * 128, n0 = blockIdx.x * 128;

    float acc[2][8][4] = {};

    auto issue = [&](int st, int k0) {
        const uint32_t base = smb + st*STG*2;
        #pragma unroll
        for (int it = 0; it < 2; ++it) {
            int id = tid + it*256;
            int r = id >> 2, cc = id & 3;                       // A: 4 chunks/row
            uint32_t d = base + (uint32_t)(r*LAS + cc*8)*2;
            const size_t off = (size_t)(m0+r)*lda + k0 + cc*8;
            CP_ASYNC16(d,            AH + off);
            CP_ASYNC16(d + ASZ*2,    AL + off);
        }
        #pragma unroll
        for (int it = 0; it < 2; ++it) {
            int id = tid + it*256;
            int r = id >> 4, cc = id & 15;                      // B: 16 chunks/row
            uint32_t d = base + 2*ASZ*2 + (uint32_t)(r*LBS + cc*8)*2;
            const size_t off = (size_t)(k0+r)*ldb + n0 + cc*8;
            CP_ASYNC16(d,            BH + off);
            CP_ASYNC16(d + BSZ*2,    BL + off);
        }
    };

    const int nk = K / 32;
    issue(0, 0);  CP_COMMIT();
    issue(1, 32); CP_COMMIT();

    for (int kt = 0; kt < nk; ++kt) {
        CP_WAIT1();
        __syncthreads();
        if (kt + 2 < nk) issue((kt+2) % 3, (kt+2)*32);
        CP_COMMIT();

        const unsigned short* Ah = sm + (kt%3)*STG;
        const unsigned short* Al = Ah + ASZ;
        const unsigned short* Bh = Al + ASZ;
        const unsigned short* Bl = Bh + BSZ;

        #pragma unroll
        for (int ks = 0; ks < 2; ++ks) {
            uint32_t ah[2][4], al[2][4];
            #pragma unroll
            for (int mt = 0; mt < 2; ++mt) {
                int r = wm*32 + mt*16 + (lane & 15);
                int c = ks*16 + ((lane >> 4) << 3);
                ldsm_x4(ah[mt], smem_u32(Ah + r*LAS + c));
                ldsm_x4(al[mt], smem_u32(Al + r*LAS + c));
            }
            #pragma unroll
            for (int np = 0; np < 4; ++np) {
                uint32_t bh[4], bl[4];
                int off = (ks*16 + (lane & 15))*LBS + wn*64 + np*16 + ((lane >> 4) << 3);
                ldsm_x4t(bh, smem_u32(Bh + off));
                ldsm_x4t(bl, smem_u32(Bl + off));
                #pragma unroll
                for (int s = 0; s < 2; ++s) {
                    const int nt = np*2 + s;
                    #pragma unroll
                    for (int mt = 0; mt < 2; ++mt) {
                        mma16816(acc[mt][nt], ah[mt], bh + s*2);
                        mma16816(acc[mt][nt], al[mt], bh + s*2);
                        mma16816(acc[mt][nt], ah[mt], bl + s*2);
                    }
                }
            }
        }
    }

    // --- epilogue ---
    #pragma unroll
    for (int mt = 0; mt < 2; ++mt) {
        #pragma unroll
        for (int nt = 0; nt < 8; ++nt) {
            const int row = m0 + wm*32 + mt*16 + (lane >> 2);
            const int col = n0 + wn*64 + nt*8 + (lane & 3)*2;
            #pragma unroll
            for (int h = 0; h < 2; ++h) {
                const int r2 = row + h*8;
                float v0 = acc[mt][nt][h*2+0];
                float v1 = acc[mt][nt][h*2+1];
                v0 += bias[col]; v1 += bias[col+1];
                if (EPI == 1) {
                    const size_t ri = (size_t)r2*ldr + col;
                    const ushort2 rh = *(const ushort2*)(RH + ri);
                    const ushort2 rl = *(const ushort2*)(RL + ri);
                    v0 += bf2f(rh.x) + bf2f(rl.x);
                    v1 += bf2f(rh.y) + bf2f(rl.y);
                    *(float2*)(Cf + (size_t)r2*ldc + col) = make_float2(v0, v1);
                } else {
                    if (EPI == 2) {
                        v0 = 0.5f*v0*(1.0f + erff(v0 * 0.70710678118654752f));
                        v1 = 0.5f*v1*(1.0f + erff(v1 * 0.70710678118654752f));
                    }
                    unsigned short h0, l0, h1, l1;
                    split1(v0, h0, l0); split1(v1, h1, l1);
                    const size_t ci = (size_t)r2*ldc + col;
                    *(ushort2*)(CH + ci) = make_ushort2(h0, h1);
                    *(ushort2*)(CL + ci) = make_ushort2(l0, l1);
                }
            }
        }
    }
}

// ---------------------------------------------------------------------------
// Fused flash attention; Q/K/V pre-split bf16 (ld = H3); ctx out as hi/lo.
// ---------------------------------------------------------------------------
#define FLASH_SMEM (6*128*(64+8)*2)   // 110592 B

__global__ void __launch_bounds__(256, 1)
flash_attn(const __nv_bfloat16* __restrict__ QKVH,
           const __nv_bfloat16* __restrict__ QKVL,
           __nv_bfloat16* __restrict__ OH, __nv_bfloat16* __restrict__ OL)
{
    constexpr int DP  = DHH + 8;
    constexpr int QSZ = 128*DP;

    extern __shared__ __align__(16) unsigned short dynsm[];
    unsigned short* Qh = dynsm;
    unsigned short* Ql = Qh + QSZ;
    unsigned short* Kh = Ql + QSZ;
    unsigned short* Kl = Kh + QSZ;
    unsigned short* Vh = Kl + QSZ;
    unsigned short* Vl = Vh + QSZ;

    const int tid = threadIdx.x, lane = tid & 31, w = tid >> 5;
    const int b = blockIdx.y / NHH, hh = blockIdx.y % NHH;
    const int q0 = blockIdx.x * 128;
    const size_t qoff = ((size_t)b*SS + q0)*H3 + hh*DHH;
    const size_t koff = (size_t)b*SS*H3 + HH + hh*DHH;
    const size_t voff = (size_t)b*SS*H3 + 2*HH + hh*DHH;

    #pragma unroll
    for (int it = 0; it < 4; ++it) {
        int id = tid + it*256;
        int r = id >> 3, c8 = id & 7;
        *(uint4*)&Qh[r*DP + c8*8] = *(const uint4*)(QKVH + qoff + (size_t)r*H3 + c8*8);
        *(uint4*)&Ql[r*DP + c8*8] = *(const uint4*)(QKVL + qoff + (size_t)r*H3 + c8*8);
    }
    __syncthreads();

    uint32_t qh[4][4], ql[4][4];
    {
        int r = w*16 + (lane & 15);
        #pragma unroll
        for (int ks = 0; ks < 4; ++ks) {
            int c = ks*16 + ((lane >> 4) << 3);
            ldsm_x4(qh[ks], smem_u32(Qh + r*DP + c));
            ldsm_x4(ql[ks], smem_u32(Ql + r*DP + c));
        }
    }

    float oacc[8][4] = {};
    float mrow[2] = {-1e30f, -1e30f};
    float lrow[2] = {0.0f, 0.0f};

    const int kb_row = (lane & 7) + ((lane & 16) >> 1);
    const int kb_col = ((lane >> 3) & 1) * 8;

    for (int j = 0; j < 4; ++j) {
        const size_t s0 = (size_t)j*128;
        #pragma unroll
        for (int it = 0; it < 4; ++it) {
            int id = tid + it*256;
            int r = id >> 3, c8 = id & 7;
            const size_t gk = koff + (s0+r)*H3 + c8*8;
            const size_t gv = voff + (s0+r)*H3 + c8*8;
            *(uint4*)&Kh[r*DP + c8*8] = *(const uint4*)(QKVH + gk);
            *(uint4*)&Kl[r*DP + c8*8] = *(const uint4*)(QKVL + gk);
            *(uint4*)&Vh[r*DP + c8*8] = *(const uint4*)(QKVH + gv);
            *(uint4*)&Vl[r*DP + c8*8] = *(const uint4*)(QKVL + gv);
        }
        __syncthreads();

        float sacc[16][4] = {};
        #pragma unroll
        for (int ks = 0; ks < 4; ++ks) {
            #pragma unroll
            for (int np = 0; np < 8; ++np) {
                uint32_t bh[4], bl[4];
                int off = (np*16 + kb_row)*DP + ks*16 + kb_col;
                ldsm_x4(bh, smem_u32(Kh + off));
                ldsm_x4(bl, smem_u32(Kl + off));
                #pragma unroll
                for (int s = 0; s < 2; ++s) {
                    int nt = np*2 + s;
                    mma16816(sacc[nt], qh[ks], bh + s*2);
                    mma16816(sacc[nt], ql[ks], bh + s*2);
                    mma16816(sacc[nt], qh[ks], bl + s*2);
                }
            }
        }
        #pragma unroll
        for (int nt = 0; nt < 16; ++nt) {
            sacc[nt][0] *= 0.125f; sacc[nt][1] *= 0.125f;
            sacc[nt][2] *= 0.125f; sacc[nt][3] *= 0.125f;
        }

        #pragma unroll
        for (int h = 0; h < 2; ++h) {
            float mx = -1e30f;
            #pragma unroll
            for (int nt = 0; nt < 16; ++nt)
                mx = fmaxf(mx, fmaxf(sacc[nt][2*h], sacc[nt][2*h+1]));
            mx = fmaxf(mx, __shfl_xor_sync(0xffffffffu, mx, 1));
            mx = fmaxf(mx, __shfl_xor_sync(0xffffffffu, mx, 2));
            float mnew = fmaxf(mrow[h], mx);
            float corr = expf(mrow[h] - mnew);
            mrow[h] = mnew;
            float sum = 0.0f;
            #pragma unroll
            for (int nt = 0; nt < 16; ++nt) {
                float p0 = expf(sacc[nt][2*h]   - mnew);
                float p1 = expf(sacc[nt][2*h+1] - mnew);
                sacc[nt][2*h] = p0; sacc[nt][2*h+1] = p1;
                sum += p0 + p1;
            }
            sum += __shfl_xor_sync(0xffffffffu, sum, 1);
            sum += __shfl_xor_sync(0xffffffffu, sum, 2);
            lrow[h] = lrow[h]*corr + sum;
            #pragma unroll
            for (int nt = 0; nt < 8; ++nt) {
                oacc[nt][2*h]   *= corr;
                oacc[nt][2*h+1] *= corr;
            }
        }

        #pragma unroll
        for (int ks = 0; ks < 8; ++ks) {
            uint32_t ph[4], pl[4];
            #pragma unroll
            for (int q = 0; q < 2; ++q) {
                #pragma unroll
                for (int hf = 0; hf < 2; ++hf) {
                    float x = sacc[2*ks+q][2*hf];
                    float y = sacc[2*ks+q][2*hf+1];
                    unsigned short hx, lx, hy, ly;
                    split1(x, hx, lx); split1(y, hy, ly);
                    ph[2*q+hf] = (uint32_t)hx | ((uint32_t)hy << 16);
                    pl[2*q+hf] = (uint32_t)lx | ((uint32_t)ly << 16);
                }
            }
            #pragma unroll
            for (int np = 0; np < 4; ++np) {
                uint32_t bh[4], bl[4];
                int off = (ks*16 + (lane & 15))*DP + np*16 + ((lane >> 4) << 3);
                ldsm_x4t(bh, smem_u32(Vh + off));
                ldsm_x4t(bl, smem_u32(Vl + off));
                #pragma unroll
                for (int s = 0; s < 2; ++s) {
                    int nt = np*2 + s;
                    mma16816(oacc[nt], ph, bh + s*2);
                    mma16816(oacc[nt], pl, bh + s*2);
                    mma16816(oacc[nt], ph, bl + s*2);
                }
            }
        }
        __syncthreads();
    }

    const size_t obase = (size_t)b*SS*HH + (size_t)hh*DHH;
    const int orow = w*16 + (lane >> 2);
    #pragma unroll
    for (int h = 0; h < 2; ++h) {
        const float inv = 1.0f / lrow[h];
        const int r = q0 + orow + h*8;
        #pragma unroll
        for (int nt = 0; nt < 8; ++nt) {
            const int c = nt*8 + (lane & 3)*2;
            unsigned short h0, l0, h1, l1;
            split1(oacc[nt][2*h]*inv,   h0, l0);
            split1(oacc[nt][2*h+1]*inv, h1, l1);
            const size_t oi = obase + (size_t)r*HH + c;
            *(ushort2*)(OH + oi) = make_ushort2(h0, h1);
            *(ushort2*)(OL + oi) = make_ushort2(l0, l1);
        }
    }
}

// ---------------------------------------------------------------------------
// LayerNorm (warp per row). SPLIT=1 -> bf16 hi/lo out; SPLIT=0 -> fp32 out.
// ---------------------------------------------------------------------------
template<int SPLIT>
__global__ void layernorm768(const float* __restrict__ X,
                             const float* __restrict__ g,
                             const float* __restrict__ b,
                             float* __restrict__ Yf,
                             __nv_bfloat16* __restrict__ YH,
                             __nv_bfloat16* __restrict__ YL, int rows)
{
    const int warp = (blockIdx.x * blockDim.x + threadIdx.x) >> 5;
    const int lane = threadIdx.x & 31;
    if (warp >= rows) return;
    const float4* x = (const float4*)(X + (size_t)warp * 768);

    float4 v[6];
    float s = 0.0f;
    #pragma unroll
    for (int i = 0; i < 6; ++i) {
        v[i] = x[lane + i*32];
        s += v[i].x + v[i].y + v[i].z + v[i].w;
    }
    #pragma unroll
    for (int o = 16; o; o >>= 1) s += __shfl_xor_sync(0xffffffffu, s, o);
    const float mean = s * (1.0f / 768.0f);

    float var = 0.0f;
    #pragma unroll
    for (int i = 0; i < 6; ++i) {
        float dx = v[i].x - mean, dy = v[i].y - mean, dz = v[i].z - mean, dw = v[i].w - mean;
        var += dx*dx + dy*dy + dz*dz + dw*dw;
    }
    #pragma unroll
    for (int o = 16; o; o >>= 1) var += __shfl_xor_sync(0xffffffffu, var, o);
    const float rs = rsqrtf(var * (1.0f / 768.0f) + 1e-12f);

    const float4* gg = (const float4*)g;
    const float4* bb = (const float4*)b;
    #pragma unroll
    for (int i = 0; i < 6; ++i) {
        const int c = lane + i*32;
        const float4 gv = gg[c], bv = bb[c];
        float4 o4;
        o4.x = (v[i].x - mean) * rs * gv.x + bv.x;
        o4.y = (v[i].y - mean) * rs * gv.y + bv.y;
        o4.z = (v[i].z - mean) * rs * gv.z + bv.z;
        o4.w = (v[i].w - mean) * rs * gv.w + bv.w;
        if (SPLIT) {
            ushort4 hi, lo; split4(o4, hi, lo);
            *(ushort4*)(YH + (size_t)warp*768 + c*4) = hi;
            *(ushort4*)(YL + (size_t)warp*768 + c*4) = lo;
        } else {
            *(float4*)(Yf + (size_t)warp*768 + c*4) = o4;
        }
    }
}

// ---------------------------------------------------------------------------
// Launch
// ---------------------------------------------------------------------------
extern "C" void kernel_launch(void* const* d_in, const int* in_sizes, int n_in,
                              void* d_out, int out_size)
{
    (void)in_sizes; (void)n_in; (void)out_size;
    const float* hs  = (const float*)d_in[0];
    const float* Wq  = (const float*)d_in[1];  const float* bq  = (const float*)d_in[2];
    const float* Wk  = (const float*)d_in[3];  const float* bk  = (const float*)d_in[4];
    const float* Wv  = (const float*)d_in[5];  const float* bv  = (const float*)d_in[6];
    const float* Wo  = (const float*)d_in[7];  const float* bo  = (const float*)d_in[8];
    const float* g1  = (const float*)d_in[9];  const float* b1  = (const float*)d_in[10];
    const float* Wi  = (const float*)d_in[11]; const float* bi  = (const float*)d_in[12];
    const float* Wo2 = (const float*)d_in[13]; const float* bo2 = (const float*)d_in[14];
    const float* g2  = (const float*)d_in[15]; const float* b2  = (const float*)d_in[16];

    __nv_bfloat16 *XH, *XL, *QKVH, *QKVL, *CH, *CL, *AH, *AL, *IH, *IL;
    __nv_bfloat16 *WqkvH, *WqkvL, *WoH, *WoL, *WiH, *WiL, *Wo2H, *Wo2L;
    float *T, *bqkv;
    cudaGetSymbolAddress((void**)&XH, g_XH);   cudaGetSymbolAddress((void**)&XL, g_XL);
    cudaGetSymbolAddress((void**)&QKVH, g_QKVH); cudaGetSymbolAddress((void**)&QKVL, g_QKVL);
    cudaGetSymbolAddress((void**)&CH, g_CH);   cudaGetSymbolAddress((void**)&CL, g_CL);
    cudaGetSymbolAddress((void**)&AH, g_AH);   cudaGetSymbolAddress((void**)&AL, g_AL);
    cudaGetSymbolAddress((void**)&IH, g_IH);   cudaGetSymbolAddress((void**)&IL, g_IL);
    cudaGetSymbolAddress((void**)&T,  g_T);    cudaGetSymbolAddress((void**)&bqkv, g_bqkv);
    cudaGetSymbolAddress((void**)&WqkvH, g_WqkvH); cudaGetSymbolAddress((void**)&WqkvL, g_WqkvL);
    cudaGetSymbolAddress((void**)&WoH, g_WoH); cudaGetSymbolAddress((void**)&WoL, g_WoL);
    cudaGetSymbolAddress((void**)&WiH, g_WiH); cudaGetSymbolAddress((void**)&WiL, g_WiL);
    cudaGetSymbolAddress((void**)&Wo2H, g_Wo2H); cudaGetSymbolAddress((void**)&Wo2L, g_Wo2L);

    cudaFuncSetAttribute(gemm_cp<0>, cudaFuncAttributeMaxDynamicSharedMemorySize, GEMM_SMEM);
    cudaFuncSetAttribute(gemm_cp<1>, cudaFuncAttributeMaxDynamicSharedMemorySize, GEMM_SMEM);
    cudaFuncSetAttribute(gemm_cp<2>, cudaFuncAttributeMaxDynamicSharedMemorySize, GEMM_SMEM);
    cudaFuncSetAttribute(flash_attn, cudaFuncAttributeMaxDynamicSharedMemorySize, FLASH_SMEM);

    // --- preprocessing: split weights + initial hidden state ---
    split_w<<<dim3(HH*HH/1024, LL), 256>>>(Wq,  WqkvH, WqkvL, HH, HH, H3, 0);
    split_w<<<dim3(HH*HH/1024, LL), 256>>>(Wk,  WqkvH, WqkvL, HH, HH, H3, HH);
    split_w<<<dim3(HH*HH/1024, LL), 256>>>(Wv,  WqkvH, WqkvL, HH, HH, H3, 2*HH);
    split_w<<<dim3(HH*HH/1024, LL), 256>>>(Wo,  WoH,   WoL,   HH, HH, HH, 0);
    split_w<<<dim3(HH*II/1024, LL), 256>>>(Wi,  WiH,   WiL,   HH, II, II, 0);
    split_w<<<dim3(II*HH/1024, LL), 256>>>(Wo2, Wo2H,  Wo2L,  II, HH, HH, 0);
    concat_bias<<<(LL*HH + 255)/256, 256>>>(bq, bk, bv, bqkv);
    split_x<<<(M0*HH/4 + 255)/256, 256>>>(hs, XH, XL, M0*HH/4);

    for (int l = 0; l < LL; ++l) {
        const __nv_bfloat16* wqkvH = WqkvH + (size_t)l*HH*H3;
        const __nv_bfloat16* wqkvL = WqkvL + (size_t)l*HH*H3;
        const __nv_bfloat16* woH   = WoH   + (size_t)l*HH*HH;
        const __nv_bfloat16* woL   = WoL   + (size_t)l*HH*HH;
        const __nv_bfloat16* wiH   = WiH   + (size_t)l*HH*II;
        const __nv_bfloat16* wiL   = WiL   + (size_t)l*HH*II;
        const __nv_bfloat16* wo2H  = Wo2H  + (size_t)l*II*HH;
        const __nv_bfloat16* wo2L  = Wo2L  + (size_t)l*II*HH;
        const float* bqkvl = bqkv + (size_t)l*H3;
        const float* bol   = bo   + (size_t)l*HH;
        const float* bil   = bi   + (size_t)l*II;
        const float* bo2l  = bo2  + (size_t)l*HH;

        // QKV projection: QKV = X @ Wqkv + bqkv  -> split out
        gemm_cp<0><<<dim3(H3/128, M0/128), 256, GEMM_SMEM>>>(
            XH, XL, HH, wqkvH, wqkvL, H3, bqkvl,
            nullptr, nullptr, 0, nullptr, QKVH, QKVL, H3, HH);

        // fused attention -> ctx (hi/lo)
        flash_attn<<<dim3(SS/128, NBA), 256, FLASH_SMEM>>>(QKVH, QKVL, CH, CL);

        // O projection + residual(X) -> T (fp32)
        gemm_cp<1><<<dim3(HH/128, M0/128), 256, GEMM_SMEM>>>(
            CH, CL, HH, woH, woL, HH, bol,
            XH, XL, HH, T, nullptr, nullptr, HH, HH);
        layernorm768<1><<<M0/8, 256>>>(T, g1 + (size_t)l*HH, b1 + (size_t)l*HH,
                                       nullptr, AH, AL, M0);

        // FFN1: I = gelu(A @ Wi + bi) -> split out
        gemm_cp<2><<<dim3(II/128, M0/128), 256, GEMM_SMEM>>>(
            AH, AL, HH, wiH, wiL, II, bil,
            nullptr, nullptr, 0, nullptr, IH, IL, II, HH);

        // FFN2 + residual(A) -> T (fp32)
        gemm_cp<1><<<dim3(HH/128, M0/128), 256, GEMM_SMEM>>>(
            IH, IL, II, wo2H, wo2L, HH, bo2l,
            AH, AL, HH, T, nullptr, nullptr, HH, II);

        if (l == LL-1) {
            layernorm768<0><<<M0/8, 256>>>(T, g2 + (size_t)l*HH, b2 + (size_t)l*HH,
                                           (float*)d_out, nullptr, nullptr, M0);
        } else {
            layernorm768<1><<<M0/8, 256>>>(T, g2 + (size_t)l*HH, b2 + (size_t)l*HH,
                                           nullptr, XH, XL, M0);
        }
    }
}